// round 5
// baseline (speedup 1.0000x reference)
#include <cuda_runtime.h>
#include <math.h>
#include <stdint.h>

#define BATCH 2
#define SEQ   2048
#define EMB   1024
#define HEADS 16
#define HDIM  64
#define M_TOT (BATCH * SEQ)   // 4096
#define QKV_N (3 * EMB)       // 3072

__device__ float g_qkv[M_TOT * QKV_N];      // [B,N,3,H,D] (tf32-rounded)
__device__ float g_attn[M_TOT * EMB];       // [B,N,C]     (tf32-rounded)
__device__ float g_xc[M_TOT * EMB];
__device__ float g_wqkvc[EMB * QKV_N];
__device__ float g_woutc[EMB * EMB];

__device__ __forceinline__ float to_tf32(float x) {
    uint32_t r;
    asm("cvt.rna.tf32.f32 %0, %1;" : "=r"(r) : "r"(__float_as_uint(x)));
    return __uint_as_float(r);
}

__device__ __forceinline__ void mma_tf32(float* c, const float* a, const float* b) {
    const uint32_t* A = (const uint32_t*)a;
    const uint32_t* B = (const uint32_t*)b;
    asm volatile(
        "mma.sync.aligned.m16n8k8.row.col.f32.tf32.tf32.f32 "
        "{%0,%1,%2,%3},{%4,%5,%6,%7},{%8,%9},{%0,%1,%2,%3};"
        : "+f"(c[0]), "+f"(c[1]), "+f"(c[2]), "+f"(c[3])
        : "r"(A[0]), "r"(A[1]), "r"(A[2]), "r"(A[3]), "r"(B[0]), "r"(B[1]));
}

__device__ __forceinline__ uint32_t smem_u32(const void* p) {
    return (uint32_t)__cvta_generic_to_shared(p);
}
__device__ __forceinline__ void cp16(uint32_t s, const void* g) {
    asm volatile("cp.async.cg.shared.global [%0], [%1], 16;" :: "r"(s), "l"(g));
}
#define CP_COMMIT() asm volatile("cp.async.commit_group;")
#define CP_WAIT2()  asm volatile("cp.async.wait_group 2;")
#define CP_WAIT3()  asm volatile("cp.async.wait_group 3;")

// ---------------------------------------------------------------------------
__global__ void cvt_tf32_kernel(const float4* __restrict__ in,
                                float4* __restrict__ out, int n4) {
    int i = blockIdx.x * blockDim.x + threadIdx.x;
    if (i < n4) {
        float4 v = in[i];
        v.x = to_tf32(v.x); v.y = to_tf32(v.y);
        v.z = to_tf32(v.z); v.w = to_tf32(v.w);
        out[i] = v;
    }
}

// ---------------------------------------------------------------------------
// TF32 GEMM: C = A[M,K] @ B[K,N] + bias. A,B tf32-rounded.
// Block 256x128, 512 threads = 16 warps (4Mx4N), warp tile 64x32,
// K-tile 16, 4-stage cp.async ring, ONE barrier per k-tile.
// ---------------------------------------------------------------------------
#define AS_STRIDE 20
#define BS_STRIDE 136
#define AS_FLOATS (256 * AS_STRIDE)            // 5120
#define BS_FLOATS (16 * BS_STRIDE)             // 2176
#define GM_STAGE  (AS_FLOATS + BS_FLOATS)      // 7296 floats
#define GEMM_SMEM_BYTES (GM_STAGE * 4 * 4)     // 116736 B

__global__ __launch_bounds__(512, 1)
void gemm_tf32_kernel(const float* __restrict__ A, const float* __restrict__ B,
                      const float* __restrict__ bias, float* __restrict__ C,
                      int M, int N, int K, int round_out) {
    extern __shared__ float sm[];

    const int tid  = threadIdx.x;
    const int lane = tid & 31;
    const int warp = tid >> 5;
    const int wm = (warp >> 2) * 64;   // 0,64,128,192
    const int wn = (warp & 3) * 32;    // 0,32,64,96
    const int m0 = blockIdx.y * 256;
    const int n0 = blockIdx.x * 128;
    const int lg = lane >> 2;
    const int lt = lane & 3;

    float c[4][4][4];
#pragma unroll
    for (int mi = 0; mi < 4; mi++)
#pragma unroll
        for (int ni = 0; ni < 4; ni++)
#pragma unroll
            for (int j = 0; j < 4; j++) c[mi][ni][j] = 0.0f;

    // A tile 256x16: 1024 float4 chunks -> 2/thread. B tile 16x128: 512 -> 1/thread.
    const int a_row = tid >> 2, a_seg = tid & 3;
    const int b_row = tid >> 5, b_seg = tid & 31;

    auto ldg_stage = [&](int s, int kt) {
        const int k0 = kt * 16;
        float* As = sm + s * GM_STAGE;
        float* Bs = As + AS_FLOATS;
#pragma unroll
        for (int r = 0; r < 2; r++) {
            int row = a_row + r * 128;
            cp16(smem_u32(&As[row * AS_STRIDE + a_seg * 4]),
                 &A[(size_t)(m0 + row) * K + k0 + a_seg * 4]);
        }
        cp16(smem_u32(&Bs[b_row * BS_STRIDE + b_seg * 4]),
             &B[(size_t)(k0 + b_row) * N + n0 + b_seg * 4]);
        CP_COMMIT();
    };

    const int NKT = K / 16;
    ldg_stage(0, 0);
    ldg_stage(1, 1);
    ldg_stage(2, 2);

    for (int t = 0; t < NKT; t++) {
        CP_WAIT2();
        __syncthreads();
        // stage (t+3)%4 == (t-1)%4: consumed at iter t-1, all warps past barrier
        if (t + 3 < NKT) ldg_stage((t + 3) & 3, t + 3);
        else CP_COMMIT();

        const float* As = sm + (t & 3) * GM_STAGE;
        const float* Bs = As + AS_FLOATS;
#pragma unroll
        for (int ks = 0; ks < 2; ks++) {
            const int kk = ks * 8;
            float a[4][4];
#pragma unroll
            for (int mi = 0; mi < 4; mi++) {
                int row = wm + mi * 16 + lg;
                int col = kk + lt;
                a[mi][0] = As[row * AS_STRIDE + col];
                a[mi][1] = As[(row + 8) * AS_STRIDE + col];
                a[mi][2] = As[row * AS_STRIDE + col + 4];
                a[mi][3] = As[(row + 8) * AS_STRIDE + col + 4];
            }
#pragma unroll
            for (int ni = 0; ni < 4; ni++) {
                float b[2];
                int col = wn + ni * 8 + lg;
                b[0] = Bs[(kk + lt) * BS_STRIDE + col];
                b[1] = Bs[(kk + lt + 4) * BS_STRIDE + col];
#pragma unroll
                for (int mi = 0; mi < 4; mi++) mma_tf32(c[mi][ni], a[mi], b);
            }
        }
    }

#pragma unroll
    for (int mi = 0; mi < 4; mi++) {
        int row = m0 + wm + mi * 16 + lg;
#pragma unroll
        for (int ni = 0; ni < 4; ni++) {
            int col = n0 + wn + ni * 8 + 2 * lt;
            float2 bv = *(const float2*)&bias[col];
            float2 r0 = make_float2(c[mi][ni][0] + bv.x, c[mi][ni][1] + bv.y);
            float2 r1 = make_float2(c[mi][ni][2] + bv.x, c[mi][ni][3] + bv.y);
            if (round_out) {
                r0.x = to_tf32(r0.x); r0.y = to_tf32(r0.y);
                r1.x = to_tf32(r1.x); r1.y = to_tf32(r1.y);
            }
            *(float2*)&C[(size_t)row * N + col] = r0;
            *(float2*)&C[(size_t)(row + 8) * N + col] = r1;
        }
    }
}

// ---------------------------------------------------------------------------
// Flash attention, TF32, Br=128, Bc=64, 4-stage cp.async ring, 1 sync/iter.
// ---------------------------------------------------------------------------
#define KSS 68
#define VSS 72
#define AT_KF (64 * KSS)
#define AT_VF (64 * VSS)
#define AT_STAGE (AT_KF + AT_VF)                 // 8960 floats
#define QS 68
#define Q_OFF (AT_STAGE * 4)
#define ATTN_SMEM_BYTES ((AT_STAGE * 4 + 128 * QS) * 4)   // 178176 B

__global__ __launch_bounds__(256, 1)
void attn_tf32_kernel(const float* __restrict__ qkv, float* __restrict__ out) {
    extern __shared__ float sm[];

    const int tid  = threadIdx.x;
    const int lane = tid & 31;
    const int warp = tid >> 5;
    const int lg = lane >> 2;
    const int lt = lane & 3;
    const int bh = blockIdx.y;
    const int b  = bh >> 4;
    const int h  = bh & 15;
    const int q0 = blockIdx.x * 128;
    const unsigned FULL = 0xffffffffu;

    const size_t base = (size_t)b * SEQ * 3 * EMB + (size_t)h * HDIM;

    auto ldg_stage = [&](int s, int it) {
        const int c0 = it * 64;
        float* Ks = sm + s * AT_STAGE;
        float* Vs = Ks + AT_KF;
#pragma unroll
        for (int r = 0; r < 4; r++) {
            int i = tid + r * 256;
            int row = i >> 4, seg = i & 15;
            size_t go = base + (size_t)(c0 + row) * 3072;
            cp16(smem_u32(&Ks[row * KSS + seg * 4]), &qkv[go + EMB + seg * 4]);
            cp16(smem_u32(&Vs[row * VSS + seg * 4]), &qkv[go + 2 * EMB + seg * 4]);
        }
        CP_COMMIT();
    };

    // Q via cp.async
    {
        float* Qs = sm + Q_OFF;
#pragma unroll
        for (int r = 0; r < 8; r++) {
            int i = tid + r * 256;
            int row = i >> 4, seg = i & 15;
            cp16(smem_u32(&Qs[row * QS + seg * 4]),
                 &qkv[base + (size_t)(q0 + row) * 3072 + seg * 4]);
        }
        CP_COMMIT();
    }
    ldg_stage(0, 0);
    ldg_stage(1, 1);
    ldg_stage(2, 2);

    CP_WAIT3();          // Q done
    __syncthreads();

    float aq[8][4];
    {
        const float* Qs = sm + Q_OFF;
        int r = warp * 16 + lg;
#pragma unroll
        for (int kd = 0; kd < 8; kd++) {
            int col = kd * 8 + lt;
            aq[kd][0] = Qs[r * QS + col];
            aq[kd][1] = Qs[(r + 8) * QS + col];
            aq[kd][2] = Qs[r * QS + col + 4];
            aq[kd][3] = Qs[(r + 8) * QS + col + 4];
        }
    }

    float o[8][4];
#pragma unroll
    for (int ni = 0; ni < 8; ni++)
#pragma unroll
        for (int j = 0; j < 4; j++) o[ni][j] = 0.0f;
    float m0r = -INFINITY, m1r = -INFINITY, l0 = 0.0f, l1 = 0.0f;
    const float scale = 0.03125f;  // EMB^-0.5 (reference scales by full C)

    const int NIT = SEQ / 64;
    const int src0 = (lane & 28) | (lt >> 1);
    const int src2 = src0 + 2;
    const bool odd = lt & 1;

    for (int t = 0; t < NIT; t++) {
        CP_WAIT2();
        __syncthreads();
        if (t + 3 < NIT) ldg_stage((t + 3) & 3, t + 3);
        else CP_COMMIT();

        const float* Ks = sm + (t & 3) * AT_STAGE;
        const float* Vs = Ks + AT_KF;

        // ---- S = Q K^T ----
        float s[8][4];
#pragma unroll
        for (int ni = 0; ni < 8; ni++)
#pragma unroll
            for (int j = 0; j < 4; j++) s[ni][j] = 0.0f;
#pragma unroll
        for (int kd = 0; kd < 8; kd++) {
#pragma unroll
            for (int ni = 0; ni < 8; ni++) {
                float bfr[2];
                int key = ni * 8 + lg;
                bfr[0] = Ks[key * KSS + kd * 8 + lt];
                bfr[1] = Ks[key * KSS + kd * 8 + lt + 4];
                mma_tf32(s[ni], aq[kd], bfr);
            }
        }

        // ---- online softmax ----
        float mr0 = -INFINITY, mr1 = -INFINITY;
#pragma unroll
        for (int ni = 0; ni < 8; ni++) {
            mr0 = fmaxf(mr0, fmaxf(s[ni][0], s[ni][1]));
            mr1 = fmaxf(mr1, fmaxf(s[ni][2], s[ni][3]));
        }
#pragma unroll
        for (int off = 1; off <= 2; off <<= 1) {
            mr0 = fmaxf(mr0, __shfl_xor_sync(FULL, mr0, off));
            mr1 = fmaxf(mr1, __shfl_xor_sync(FULL, mr1, off));
        }
        float mn0 = fmaxf(m0r, mr0 * scale);
        float mn1 = fmaxf(m1r, mr1 * scale);
        float f0 = __expf(m0r - mn0);
        float f1 = __expf(m1r - mn1);
        m0r = mn0; m1r = mn1;

        float rs0 = 0.0f, rs1 = 0.0f;
#pragma unroll
        for (int ni = 0; ni < 8; ni++) {
            float p0 = __expf(s[ni][0] * scale - mn0);
            float p1 = __expf(s[ni][1] * scale - mn0);
            float p2 = __expf(s[ni][2] * scale - mn1);
            float p3 = __expf(s[ni][3] * scale - mn1);
            rs0 += p0 + p1;
            rs1 += p2 + p3;
            s[ni][0] = to_tf32(p0); s[ni][1] = to_tf32(p1);
            s[ni][2] = to_tf32(p2); s[ni][3] = to_tf32(p3);
            o[ni][0] *= f0; o[ni][1] *= f0;
            o[ni][2] *= f1; o[ni][3] *= f1;
        }
#pragma unroll
        for (int off = 1; off <= 2; off <<= 1) {
            rs0 += __shfl_xor_sync(FULL, rs0, off);
            rs1 += __shfl_xor_sync(FULL, rs1, off);
        }
        l0 = l0 * f0 + rs0;
        l1 = l1 * f1 + rs1;

        // ---- O += P V (P fragments via shuffles) ----
#pragma unroll
        for (int kk = 0; kk < 8; kk++) {
            float v00 = __shfl_sync(FULL, s[kk][0], src0);
            float v01 = __shfl_sync(FULL, s[kk][1], src0);
            float v02 = __shfl_sync(FULL, s[kk][2], src0);
            float v03 = __shfl_sync(FULL, s[kk][3], src0);
            float v20 = __shfl_sync(FULL, s[kk][0], src2);
            float v21 = __shfl_sync(FULL, s[kk][1], src2);
            float v22 = __shfl_sync(FULL, s[kk][2], src2);
            float v23 = __shfl_sync(FULL, s[kk][3], src2);
            float pa[4];
            pa[0] = odd ? v01 : v00;
            pa[1] = odd ? v03 : v02;
            pa[2] = odd ? v21 : v20;
            pa[3] = odd ? v23 : v22;
#pragma unroll
            for (int ni = 0; ni < 8; ni++) {
                float bfr[2];
                int d = ni * 8 + lg;
                bfr[0] = Vs[(kk * 8 + lt) * VSS + d];
                bfr[1] = Vs[(kk * 8 + lt + 4) * VSS + d];
                mma_tf32(o[ni], pa, bfr);
            }
        }
    }

    // ---- normalize, round (GEMM3 consumes), write [B,N,C] ----
    float inv0 = 1.0f / l0, inv1 = 1.0f / l1;
    int r = q0 + warp * 16 + lg;
#pragma unroll
    for (int ni = 0; ni < 8; ni++) {
        int col = h * HDIM + ni * 8 + 2 * lt;
        *(float2*)&out[((size_t)b * SEQ + r) * EMB + col] =
            make_float2(to_tf32(o[ni][0] * inv0), to_tf32(o[ni][1] * inv0));
        *(float2*)&out[((size_t)b * SEQ + r + 8) * EMB + col] =
            make_float2(to_tf32(o[ni][2] * inv1), to_tf32(o[ni][3] * inv1));
    }
}

// ---------------------------------------------------------------------------
extern "C" void kernel_launch(void* const* d_in, const int* in_sizes, int n_in,
                              void* d_out, int out_size) {
    const float* x     = (const float*)d_in[0];
    const float* W_qkv = (const float*)d_in[1];
    const float* b_qkv = (const float*)d_in[2];
    const float* W_out = (const float*)d_in[3];
    const float* b_out = (const float*)d_in[4];
    float* out = (float*)d_out;

    float *qkv, *attn, *xc, *wqkvc, *woutc;
    cudaGetSymbolAddress((void**)&qkv, g_qkv);
    cudaGetSymbolAddress((void**)&attn, g_attn);
    cudaGetSymbolAddress((void**)&xc, g_xc);
    cudaGetSymbolAddress((void**)&wqkvc, g_wqkvc);
    cudaGetSymbolAddress((void**)&woutc, g_woutc);

    cudaFuncSetAttribute(gemm_tf32_kernel,
                         cudaFuncAttributeMaxDynamicSharedMemorySize,
                         GEMM_SMEM_BYTES);
    cudaFuncSetAttribute(attn_tf32_kernel,
                         cudaFuncAttributeMaxDynamicSharedMemorySize,
                         ATTN_SMEM_BYTES);

    // 0) tf32-round inputs once
    {
        int n4;
        n4 = M_TOT * EMB / 4;
        cvt_tf32_kernel<<<(n4 + 255) / 256, 256>>>((const float4*)x, (float4*)xc, n4);
        n4 = EMB * QKV_N / 4;
        cvt_tf32_kernel<<<(n4 + 255) / 256, 256>>>((const float4*)W_qkv, (float4*)wqkvc, n4);
        n4 = EMB * EMB / 4;
        cvt_tf32_kernel<<<(n4 + 255) / 256, 256>>>((const float4*)W_out, (float4*)woutc, n4);
    }

    // 1) QKV projection
    gemm_tf32_kernel<<<dim3(QKV_N / 128, M_TOT / 256), 512, GEMM_SMEM_BYTES>>>(
        xc, wqkvc, b_qkv, qkv, M_TOT, QKV_N, EMB, 1);
    // 2) Attention
    attn_tf32_kernel<<<dim3(SEQ / 128, BATCH * HEADS), 256, ATTN_SMEM_BYTES>>>(
        qkv, attn);
    // 3) Output projection
    gemm_tf32_kernel<<<dim3(EMB / 128, M_TOT / 256), 512, GEMM_SMEM_BYTES>>>(
        attn, woutc, b_out, out, M_TOT, EMB, EMB, 0);
}

// round 7
// speedup vs baseline: 1.0345x; 1.0345x over previous
#include <cuda_runtime.h>
#include <math.h>
#include <stdint.h>

#define BATCH 2
#define SEQ   2048
#define EMB   1024
#define HEADS 16
#define HDIM  64
#define M_TOT (BATCH * SEQ)   // 4096
#define QKV_N (3 * EMB)       // 3072

__device__ float g_qkv[M_TOT * QKV_N];      // [B,N,3,H,D] (tf32-rounded)
__device__ float g_attn[M_TOT * EMB];       // [B,N,C]     (tf32-rounded)
__device__ float g_xc[M_TOT * EMB];         // x tf32-rounded
__device__ float g_wqkvt[QKV_N * EMB];      // W_qkv^T [N,K] tf32-rounded
__device__ float g_woutt[EMB * EMB];        // W_out^T [N,K] tf32-rounded
__device__ float g_vt[M_TOT * EMB];         // V transposed [B,H,D,SEQ]

// ---------------------------------------------------------------------------
// helpers
// ---------------------------------------------------------------------------
__device__ __forceinline__ float to_tf32(float x) {
    uint32_t r;
    asm("cvt.rna.tf32.f32 %0, %1;" : "=r"(r) : "r"(__float_as_uint(x)));
    return __uint_as_float(r);
}
__device__ __forceinline__ void mma_tf32(float* c, const float* a, const float* b) {
    const uint32_t* A = (const uint32_t*)a;
    const uint32_t* B = (const uint32_t*)b;
    asm volatile(
        "mma.sync.aligned.m16n8k8.row.col.f32.tf32.tf32.f32 "
        "{%0,%1,%2,%3},{%4,%5,%6,%7},{%8,%9},{%0,%1,%2,%3};"
        : "+f"(c[0]), "+f"(c[1]), "+f"(c[2]), "+f"(c[3])
        : "r"(A[0]), "r"(A[1]), "r"(A[2]), "r"(A[3]), "r"(B[0]), "r"(B[1]));
}
// tf32-as-b16 ldmatrix: lane l gets element [row l>>2][tf32 col l&3] per matrix
__device__ __forceinline__ void ldsm4(float* r, uint32_t saddr) {
    uint32_t* u = (uint32_t*)r;
    asm volatile(
        "ldmatrix.sync.aligned.m8n8.x4.shared.b16 {%0,%1,%2,%3}, [%4];"
        : "=r"(u[0]), "=r"(u[1]), "=r"(u[2]), "=r"(u[3]) : "r"(saddr));
}
__device__ __forceinline__ uint32_t smem_u32(const void* p) {
    return (uint32_t)__cvta_generic_to_shared(p);
}
__device__ __forceinline__ void cp16(uint32_t s, const void* g) {
    asm volatile("cp.async.cg.shared.global [%0], [%1], 16;" :: "r"(s), "l"(g));
}
#define CP_COMMIT() asm volatile("cp.async.commit_group;")
#define CP_WAIT2()  asm volatile("cp.async.wait_group 2;")
#define CP_WAIT3()  asm volatile("cp.async.wait_group 3;")

// ---------------------------------------------------------------------------
// prep kernels
// ---------------------------------------------------------------------------
__global__ void cvt_tf32_kernel(const float4* __restrict__ in,
                                float4* __restrict__ out, int n4) {
    int i = blockIdx.x * blockDim.x + threadIdx.x;
    if (i < n4) {
        float4 v = in[i];
        v.x = to_tf32(v.x); v.y = to_tf32(v.y);
        v.z = to_tf32(v.z); v.w = to_tf32(v.w);
        out[i] = v;
    }
}

// out[n][k] = round(in[k][n]);  in: [K,N] row-major -> out: [N,K] row-major
__global__ void transpose_tf32_kernel(const float* __restrict__ in,
                                      float* __restrict__ out, int K, int N) {
    __shared__ float t[32][33];
    int n0 = blockIdx.x * 32, k0 = blockIdx.y * 32;
    int tx = threadIdx.x, ty = threadIdx.y;   // 32 x 8
#pragma unroll
    for (int j = 0; j < 32; j += 8)
        t[ty + j][tx] = in[(size_t)(k0 + ty + j) * N + n0 + tx];
    __syncthreads();
#pragma unroll
    for (int j = 0; j < 32; j += 8)
        out[(size_t)(n0 + ty + j) * K + k0 + tx] = to_tf32(t[tx][ty + j]);
}

// vt[b][h][d][n] = qkv V-part (already rounded by GEMM1 epilogue)
__global__ void transpose_v_kernel(const float* __restrict__ qkv,
                                   float* __restrict__ vt) {
    __shared__ float t[32][33];
    int n0 = blockIdx.x * 32, d0 = blockIdx.y * 32;
    int bh = blockIdx.z;
    int b = bh >> 4, h = bh & 15;
    int tx = threadIdx.x, ty = threadIdx.y;
    const size_t inbase = (size_t)b * SEQ * 3072 + 2048 + (size_t)h * 64;
#pragma unroll
    for (int j = 0; j < 32; j += 8)
        t[ty + j][tx] = qkv[inbase + (size_t)(n0 + ty + j) * 3072 + d0 + tx];
    __syncthreads();
    const size_t outbase = (size_t)bh * 64 * SEQ;
#pragma unroll
    for (int j = 0; j < 32; j += 8)
        vt[outbase + (size_t)(d0 + ty + j) * SEQ + n0 + tx] = t[tx][ty + j];
}

// ---------------------------------------------------------------------------
// TF32 GEMM via ldmatrix: C[M,N] = A[M,K] @ Bt[N,K]^T + bias
// Block 256x128, 8 warps (4Mx2N), warp tile 64x64, K-tile 16,
// 3-stage cp.async, both tiles [rows][16k] with stride 20 floats.
// ---------------------------------------------------------------------------
#define TS 20                                // floats per tile row
#define A_FLOATS (256 * TS)                  // 5120
#define B_FLOATS (128 * TS)                  // 2560
#define G_STAGE  (A_FLOATS + B_FLOATS)       // 7680 floats
#define GEMM_SMEM_BYTES (G_STAGE * 3 * 4)    // 92160

__global__ __launch_bounds__(256, 1)
void gemm_tf32_kernel(const float* __restrict__ A, const float* __restrict__ Bt,
                      const float* __restrict__ bias, float* __restrict__ C,
                      int M, int N, int K, int round_out) {
    extern __shared__ float sm[];

    const int tid  = threadIdx.x;
    const int lane = tid & 31;
    const int warp = tid >> 5;
    const int wm = (warp >> 1) * 64;   // 0,64,128,192
    const int wn = (warp & 1) * 64;    // 0,64
    const int m0 = blockIdx.y * 256;
    const int n0 = blockIdx.x * 128;
    const int lt = lane & 3;

    float c[4][8][4];
#pragma unroll
    for (int mi = 0; mi < 4; mi++)
#pragma unroll
        for (int ni = 0; ni < 8; ni++)
#pragma unroll
            for (int j = 0; j < 4; j++) c[mi][ni][j] = 0.0f;

    // ldmatrix per-thread base addresses (bytes)
    const uint32_t sb = smem_u32(sm);
    // A: matrices (mlo,kl),(mhi,kl),(mlo,kh),(mhi,kh) across lane octets
    const uint32_t a_base = sb +
        (uint32_t)((wm + ((lane >> 3) & 1) * 8 + (lane & 7)) * TS * 4 +
                   ((lane >> 4) & 1) * 16);
    // B: matrices (n,kl),(n,kh),(n+8,kl),(n+8,kh)
    const uint32_t b_base = sb + A_FLOATS * 4 +
        (uint32_t)((wn + ((lane >> 3) & 2) * 4 + (lane & 7)) * TS * 4 +
                   ((lane >> 3) & 1) * 16);

    const int a_row = tid >> 2, a_seg = tid & 3;

    auto ldg_stage = [&](int s, int kt) {
        const int k0 = kt * 16;
        float* As = sm + s * G_STAGE;
        float* Bs = As + A_FLOATS;
#pragma unroll
        for (int r = 0; r < 4; r++) {
            int row = a_row + r * 64;
            cp16(smem_u32(&As[row * TS + a_seg * 4]),
                 &A[(size_t)(m0 + row) * K + k0 + a_seg * 4]);
        }
#pragma unroll
        for (int r = 0; r < 2; r++) {
            int row = a_row + r * 64;
            cp16(smem_u32(&Bs[row * TS + a_seg * 4]),
                 &Bt[(size_t)(n0 + row) * K + k0 + a_seg * 4]);
        }
        CP_COMMIT();
    };

    const int NKT = K / 16;
    ldg_stage(0, 0);
    ldg_stage(1, 1);
    ldg_stage(2, 2);

    for (int t = 0; t < NKT; t++) {
        CP_WAIT2();
        __syncthreads();

        const uint32_t soff = (uint32_t)((t % 3) * G_STAGE * 4);
#pragma unroll
        for (int ks = 0; ks < 2; ks++) {
            float a[4][4];
#pragma unroll
            for (int mi = 0; mi < 4; mi++)
                ldsm4(a[mi], a_base + soff + mi * 16 * TS * 4 + ks * 32);
            float bf[4][4];
#pragma unroll
            for (int nip = 0; nip < 4; nip++)
                ldsm4(bf[nip], b_base + soff + nip * 16 * TS * 4 + ks * 32);
#pragma unroll
            for (int nip = 0; nip < 4; nip++)
#pragma unroll
                for (int mi = 0; mi < 4; mi++) {
                    mma_tf32(c[mi][2 * nip + 0], a[mi], &bf[nip][0]);
                    mma_tf32(c[mi][2 * nip + 1], a[mi], &bf[nip][2]);
                }
        }
        __syncthreads();
        if (t + 3 < NKT) ldg_stage(t % 3, t + 3);
        else CP_COMMIT();
    }

    const int lg = lane >> 2;
#pragma unroll
    for (int mi = 0; mi < 4; mi++) {
        int row = m0 + wm + mi * 16 + lg;
#pragma unroll
        for (int ni = 0; ni < 8; ni++) {
            int col = n0 + wn + ni * 8 + 2 * lt;
            float2 bv = *(const float2*)&bias[col];
            float2 r0 = make_float2(c[mi][ni][0] + bv.x, c[mi][ni][1] + bv.y);
            float2 r1 = make_float2(c[mi][ni][2] + bv.x, c[mi][ni][3] + bv.y);
            if (round_out) {
                r0.x = to_tf32(r0.x); r0.y = to_tf32(r0.y);
                r1.x = to_tf32(r1.x); r1.y = to_tf32(r1.y);
            }
            *(float2*)&C[(size_t)row * N + col] = r0;
            *(float2*)&C[(size_t)(row + 8) * N + col] = r1;
        }
    }
}

// ---------------------------------------------------------------------------
// Flash attention, TF32, ldmatrix for Q/K/V fragments.
// Br=128, Bc=64, 3-stage cp.async, P via shuffles. V from vt [b,h,d,n].
// ---------------------------------------------------------------------------
#define KSS 68
#define VSS 68
#define AT_KF (64 * KSS)
#define AT_VF (64 * VSS)
#define AT_STAGE (AT_KF + AT_VF)             // 8704 floats
#define QS 68
#define Q_OFF (AT_STAGE * 3)
#define ATTN_SMEM_BYTES ((AT_STAGE * 3 + 128 * QS) * 4)   // 139264

__global__ __launch_bounds__(256, 1)
void attn_tf32_kernel(const float* __restrict__ qkv, const float* __restrict__ vt,
                      float* __restrict__ out) {
    extern __shared__ float sm[];

    const int tid  = threadIdx.x;
    const int lane = tid & 31;
    const int warp = tid >> 5;
    const int lg = lane >> 2;
    const int lt = lane & 3;
    const int bh = blockIdx.y;
    const int b  = bh >> 4;
    const int h  = bh & 15;
    const int q0 = blockIdx.x * 128;
    const unsigned FULL = 0xffffffffu;

    const size_t base  = (size_t)b * SEQ * 3 * EMB + (size_t)h * HDIM;
    const size_t vbase = (size_t)bh * 64 * SEQ;

    auto ldg_stage = [&](int s, int it) {
        const int c0 = it * 64;
        float* Ks = sm + s * AT_STAGE;
        float* Vs = Ks + AT_KF;
#pragma unroll
        for (int r = 0; r < 4; r++) {
            int i = tid + r * 256;
            int row = i >> 4, seg = i & 15;
            cp16(smem_u32(&Ks[row * KSS + seg * 4]),
                 &qkv[base + (size_t)(c0 + row) * 3072 + EMB + seg * 4]);
            cp16(smem_u32(&Vs[row * VSS + seg * 4]),
                 &vt[vbase + (size_t)row * SEQ + c0 + seg * 4]);
        }
        CP_COMMIT();
    };

    {
        float* Qs = sm + Q_OFF;
#pragma unroll
        for (int r = 0; r < 8; r++) {
            int i = tid + r * 256;
            int row = i >> 4, seg = i & 15;
            cp16(smem_u32(&Qs[row * QS + seg * 4]),
                 &qkv[base + (size_t)(q0 + row) * 3072 + seg * 4]);
        }
        CP_COMMIT();
    }
    ldg_stage(0, 0);
    ldg_stage(1, 1);
    ldg_stage(2, 2);

    CP_WAIT3();
    __syncthreads();

    const uint32_t sb = smem_u32(sm);
    // Q A-frag ldmatrix base: matrices (mlo,kl),(mhi,kl),(mlo,kh),(mhi,kh)
    const uint32_t q_base = sb + Q_OFF * 4 +
        (uint32_t)((warp * 16 + ((lane >> 3) & 1) * 8 + (lane & 7)) * QS * 4 +
                   ((lane >> 4) & 1) * 16);
    // K/V B-frag ldmatrix base: matrices (r,kl),(r,kh),(r+8,kl),(r+8,kh)
    const uint32_t kv_row = (uint32_t)((((lane >> 3) & 2) * 4 + (lane & 7)));
    const uint32_t k_base = sb + kv_row * KSS * 4 + ((lane >> 3) & 1) * 16;
    const uint32_t v_base = sb + AT_KF * 4 + kv_row * VSS * 4 + ((lane >> 3) & 1) * 16;

    float aq[8][4];
#pragma unroll
    for (int kd = 0; kd < 8; kd++)
        ldsm4(aq[kd], q_base + kd * 32);

    float o[8][4];
#pragma unroll
    for (int ni = 0; ni < 8; ni++)
#pragma unroll
        for (int j = 0; j < 4; j++) o[ni][j] = 0.0f;
    float m0r = -INFINITY, m1r = -INFINITY, l0 = 0.0f, l1 = 0.0f;
    const float scale = 0.03125f;  // EMB^-0.5 (reference scales by full C)

    const int NIT = SEQ / 64;
    const int src0 = (lane & 28) | (lt >> 1);
    const int src2 = src0 + 2;
    const bool odd = lt & 1;

    for (int t = 0; t < NIT; t++) {
        CP_WAIT2();
        __syncthreads();

        const uint32_t soff = (uint32_t)((t % 3) * AT_STAGE * 4);

        // ---- S = Q K^T ----
        float s[8][4];
#pragma unroll
        for (int ni = 0; ni < 8; ni++)
#pragma unroll
            for (int j = 0; j < 4; j++) s[ni][j] = 0.0f;
#pragma unroll
        for (int kd = 0; kd < 8; kd++) {
            float bk[4][4];
#pragma unroll
            for (int nip = 0; nip < 4; nip++)
                ldsm4(bk[nip], k_base + soff + nip * 16 * KSS * 4 + kd * 32);
#pragma unroll
            for (int nip = 0; nip < 4; nip++) {
                mma_tf32(s[2 * nip + 0], aq[kd], &bk[nip][0]);
                mma_tf32(s[2 * nip + 1], aq[kd], &bk[nip][2]);
            }
        }

        // ---- online softmax ----
        float mr0 = -INFINITY, mr1 = -INFINITY;
#pragma unroll
        for (int ni = 0; ni < 8; ni++) {
            mr0 = fmaxf(mr0, fmaxf(s[ni][0], s[ni][1]));
            mr1 = fmaxf(mr1, fmaxf(s[ni][2], s[ni][3]));
        }
#pragma unroll
        for (int off = 1; off <= 2; off <<= 1) {
            mr0 = fmaxf(mr0, __shfl_xor_sync(FULL, mr0, off));
            mr1 = fmaxf(mr1, __shfl_xor_sync(FULL, mr1, off));
        }
        float mn0 = fmaxf(m0r, mr0 * scale);
        float mn1 = fmaxf(m1r, mr1 * scale);
        float f0 = __expf(m0r - mn0);
        float f1 = __expf(m1r - mn1);
        m0r = mn0; m1r = mn1;

        float rs0 = 0.0f, rs1 = 0.0f;
#pragma unroll
        for (int ni = 0; ni < 8; ni++) {
            float p0 = __expf(s[ni][0] * scale - mn0);
            float p1 = __expf(s[ni][1] * scale - mn0);
            float p2 = __expf(s[ni][2] * scale - mn1);
            float p3 = __expf(s[ni][3] * scale - mn1);
            rs0 += p0 + p1;
            rs1 += p2 + p3;
            s[ni][0] = to_tf32(p0); s[ni][1] = to_tf32(p1);
            s[ni][2] = to_tf32(p2); s[ni][3] = to_tf32(p3);
            o[ni][0] *= f0; o[ni][1] *= f0;
            o[ni][2] *= f1; o[ni][3] *= f1;
        }
#pragma unroll
        for (int off = 1; off <= 2; off <<= 1) {
            rs0 += __shfl_xor_sync(FULL, rs0, off);
            rs1 += __shfl_xor_sync(FULL, rs1, off);
        }
        l0 = l0 * f0 + rs0;
        l1 = l1 * f1 + rs1;

        // ---- O += P V (P a-frags via shuffles, V b-frags via ldmatrix) ----
#pragma unroll
        for (int kk = 0; kk < 8; kk++) {
            float v00 = __shfl_sync(FULL, s[kk][0], src0);
            float v01 = __shfl_sync(FULL, s[kk][1], src0);
            float v02 = __shfl_sync(FULL, s[kk][2], src0);
            float v03 = __shfl_sync(FULL, s[kk][3], src0);
            float v20 = __shfl_sync(FULL, s[kk][0], src2);
            float v21 = __shfl_sync(FULL, s[kk][1], src2);
            float v22 = __shfl_sync(FULL, s[kk][2], src2);
            float v23 = __shfl_sync(FULL, s[kk][3], src2);
            float pa[4];
            pa[0] = odd ? v01 : v00;
            pa[1] = odd ? v03 : v02;
            pa[2] = odd ? v21 : v20;
            pa[3] = odd ? v23 : v22;
            float bv[4][4];
#pragma unroll
            for (int nip = 0; nip < 4; nip++)
                ldsm4(bv[nip], v_base + soff + nip * 16 * VSS * 4 + kk * 32);
#pragma unroll
            for (int nip = 0; nip < 4; nip++) {
                mma_tf32(o[2 * nip + 0], pa, &bv[nip][0]);
                mma_tf32(o[2 * nip + 1], pa, &bv[nip][2]);
            }
        }
        __syncthreads();
        if (t + 3 < NIT) ldg_stage(t % 3, t + 3);
        else CP_COMMIT();
    }

    // ---- normalize, round (GEMM3 consumes), write [B,N,C] ----
    float inv0 = 1.0f / l0, inv1 = 1.0f / l1;
    int r = q0 + warp * 16 + lg;
#pragma unroll
    for (int ni = 0; ni < 8; ni++) {
        int col = h * HDIM + ni * 8 + 2 * lt;
        *(float2*)&out[((size_t)b * SEQ + r) * EMB + col] =
            make_float2(to_tf32(o[ni][0] * inv0), to_tf32(o[ni][1] * inv0));
        *(float2*)&out[((size_t)b * SEQ + r + 8) * EMB + col] =
            make_float2(to_tf32(o[ni][2] * inv1), to_tf32(o[ni][3] * inv1));
    }
}

// ---------------------------------------------------------------------------
extern "C" void kernel_launch(void* const* d_in, const int* in_sizes, int n_in,
                              void* d_out, int out_size) {
    const float* x     = (const float*)d_in[0];
    const float* W_qkv = (const float*)d_in[1];
    const float* b_qkv = (const float*)d_in[2];
    const float* W_out = (const float*)d_in[3];
    const float* b_out = (const float*)d_in[4];
    float* out = (float*)d_out;

    float *qkv, *attn, *xc, *wqkvt, *woutt, *vt;
    cudaGetSymbolAddress((void**)&qkv, g_qkv);
    cudaGetSymbolAddress((void**)&attn, g_attn);
    cudaGetSymbolAddress((void**)&xc, g_xc);
    cudaGetSymbolAddress((void**)&wqkvt, g_wqkvt);
    cudaGetSymbolAddress((void**)&woutt, g_woutt);
    cudaGetSymbolAddress((void**)&vt, g_vt);

    cudaFuncSetAttribute(gemm_tf32_kernel,
                         cudaFuncAttributeMaxDynamicSharedMemorySize,
                         GEMM_SMEM_BYTES);
    cudaFuncSetAttribute(attn_tf32_kernel,
                         cudaFuncAttributeMaxDynamicSharedMemorySize,
                         ATTN_SMEM_BYTES);

    // 0) prep: round x; transpose+round weights to [N,K]
    {
        int n4 = M_TOT * EMB / 4;
        cvt_tf32_kernel<<<(n4 + 255) / 256, 256>>>((const float4*)x, (float4*)xc, n4);
        transpose_tf32_kernel<<<dim3(QKV_N / 32, EMB / 32), dim3(32, 8)>>>(
            W_qkv, wqkvt, EMB, QKV_N);
        transpose_tf32_kernel<<<dim3(EMB / 32, EMB / 32), dim3(32, 8)>>>(
            W_out, woutt, EMB, EMB);
    }

    // 1) QKV projection (epilogue rounds output)
    gemm_tf32_kernel<<<dim3(QKV_N / 128, M_TOT / 256), 256, GEMM_SMEM_BYTES>>>(
        xc, wqkvt, b_qkv, qkv, M_TOT, QKV_N, EMB, 1);
    // 1b) transpose V-part for ldmatrix-friendly attention
    transpose_v_kernel<<<dim3(SEQ / 32, HDIM / 32, BATCH * HEADS), dim3(32, 8)>>>(
        qkv, vt);
    // 2) Attention
    attn_tf32_kernel<<<dim3(SEQ / 128, BATCH * HEADS), 256, ATTN_SMEM_BYTES>>>(
        qkv, vt, attn);
    // 3) Output projection (final fp32)
    gemm_tf32_kernel<<<dim3(EMB / 128, M_TOT / 256), 256, GEMM_SMEM_BYTES>>>(
        attn, woutt, b_out, out, M_TOT, EMB, EMB, 0);
}

// round 8
// speedup vs baseline: 1.8699x; 1.8076x over previous
#include <cuda_runtime.h>
#include <cuda_fp16.h>
#include <math.h>
#include <stdint.h>

#define BATCH 2
#define SEQ   2048
#define EMB   1024
#define HEADS 16
#define HDIM  64
#define M_TOT (BATCH * SEQ)   // 4096
#define QKV_N (3 * EMB)       // 3072

__device__ __half g_qkv[M_TOT * QKV_N];     // [B,N,3,H,D] fp16
__device__ __half g_attn[M_TOT * EMB];      // [B,N,C] fp16
__device__ __half g_xh[M_TOT * EMB];        // x fp16
__device__ __half g_wqkvt[QKV_N * EMB];     // W_qkv^T [N,K] fp16
__device__ __half g_woutt[EMB * EMB];       // W_out^T [N,K] fp16
__device__ __half g_vt[M_TOT * EMB];        // V transposed [B,H,D,SEQ] fp16

// ---------------------------------------------------------------------------
// helpers
// ---------------------------------------------------------------------------
__device__ __forceinline__ void mma_fp16(float* c, const uint32_t* a,
                                         const uint32_t* b) {
    asm volatile(
        "mma.sync.aligned.m16n8k16.row.col.f32.f16.f16.f32 "
        "{%0,%1,%2,%3},{%4,%5,%6,%7},{%8,%9},{%0,%1,%2,%3};"
        : "+f"(c[0]), "+f"(c[1]), "+f"(c[2]), "+f"(c[3])
        : "r"(a[0]), "r"(a[1]), "r"(a[2]), "r"(a[3]), "r"(b[0]), "r"(b[1]));
}
__device__ __forceinline__ void ldsm4(uint32_t* u, uint32_t saddr) {
    asm volatile(
        "ldmatrix.sync.aligned.m8n8.x4.shared.b16 {%0,%1,%2,%3}, [%4];"
        : "=r"(u[0]), "=r"(u[1]), "=r"(u[2]), "=r"(u[3]) : "r"(saddr));
}
__device__ __forceinline__ uint32_t smem_u32(const void* p) {
    return (uint32_t)__cvta_generic_to_shared(p);
}
__device__ __forceinline__ void cp16(uint32_t s, const void* g) {
    asm volatile("cp.async.cg.shared.global [%0], [%1], 16;" :: "r"(s), "l"(g));
}
#define CP_COMMIT() asm volatile("cp.async.commit_group;")
#define CP_WAIT2()  asm volatile("cp.async.wait_group 2;")
#define CP_WAIT3()  asm volatile("cp.async.wait_group 3;")
__device__ __forceinline__ uint32_t packh2(float lo, float hi) {
    __half2 h = __floats2half2_rn(lo, hi);
    return *(uint32_t*)&h;
}

// ---------------------------------------------------------------------------
// prep kernels
// ---------------------------------------------------------------------------
__global__ void cvt_h_kernel(const float4* __restrict__ in,
                             uint2* __restrict__ out, int n4) {
    int i = blockIdx.x * blockDim.x + threadIdx.x;
    if (i < n4) {
        float4 v = in[i];
        uint2 o;
        o.x = packh2(v.x, v.y);
        o.y = packh2(v.z, v.w);
        out[i] = o;
    }
}

// out[n][k] = half(in[k][n]);  in: [K,N] fp32 row-major -> out: [N,K] fp16
__global__ void transpose_h_kernel(const float* __restrict__ in,
                                   __half* __restrict__ out, int K, int N) {
    __shared__ float t[32][33];
    int n0 = blockIdx.x * 32, k0 = blockIdx.y * 32;
    int tx = threadIdx.x, ty = threadIdx.y;   // 32 x 8
#pragma unroll
    for (int j = 0; j < 32; j += 8)
        t[ty + j][tx] = in[(size_t)(k0 + ty + j) * N + n0 + tx];
    __syncthreads();
#pragma unroll
    for (int j = 0; j < 32; j += 8)
        out[(size_t)(n0 + ty + j) * K + k0 + tx] = __float2half_rn(t[tx][ty + j]);
}

// vt[bh][d][n] = qkv V-part (fp16 passthrough)
__global__ void transpose_v_kernel(const __half* __restrict__ qkv,
                                   __half* __restrict__ vt) {
    __shared__ __half t[32][34];
    int n0 = blockIdx.x * 32, d0 = blockIdx.y * 32;
    int bh = blockIdx.z;
    int b = bh >> 4, h = bh & 15;
    int tx = threadIdx.x, ty = threadIdx.y;
    const size_t inbase = (size_t)b * SEQ * 3072 + 2048 + (size_t)h * 64;
#pragma unroll
    for (int j = 0; j < 32; j += 8)
        t[ty + j][tx] = qkv[inbase + (size_t)(n0 + ty + j) * 3072 + d0 + tx];
    __syncthreads();
    const size_t outbase = (size_t)bh * 64 * SEQ;
#pragma unroll
    for (int j = 0; j < 32; j += 8)
        vt[outbase + (size_t)(d0 + ty + j) * SEQ + n0 + tx] = t[tx][ty + j];
}

// ---------------------------------------------------------------------------
// FP16 GEMM: C[M,N] = A[M,K] @ Bt[N,K]^T + bias
// Block 256x128, 8 warps (4Mx2N), warp tile 64x64, K-tile 32,
// 3-stage cp.async, ldmatrix fragments, mma.m16n8k16.
// ---------------------------------------------------------------------------
#define AS_H 40                                   // halves per row (32 + 8 pad)
#define A_HALVES (256 * AS_H)                     // 10240
#define B_HALVES (128 * AS_H)                     // 5120
#define G_STAGE_H (A_HALVES + B_HALVES)           // 15360 halves
#define GEMM_SMEM_BYTES (G_STAGE_H * 3 * 2)       // 92160 B

template <typename OT>
__global__ __launch_bounds__(256, 1)
void gemm_fp16_kernel(const __half* __restrict__ A, const __half* __restrict__ Bt,
                      const float* __restrict__ bias, OT* __restrict__ C,
                      int M, int N, int K) {
    extern __shared__ __half smh[];

    const int tid  = threadIdx.x;
    const int lane = tid & 31;
    const int warp = tid >> 5;
    const int wm = (warp >> 1) * 64;
    const int wn = (warp & 1) * 64;
    const int m0 = blockIdx.y * 256;
    const int n0 = blockIdx.x * 128;

    float c[4][8][4];
#pragma unroll
    for (int mi = 0; mi < 4; mi++)
#pragma unroll
        for (int ni = 0; ni < 8; ni++)
#pragma unroll
            for (int j = 0; j < 4; j++) c[mi][ni][j] = 0.0f;

    const uint32_t sb = smem_u32(smh);
    // A frag base: matrices (m0-7,k0-7),(m8-15,k0-7),(m0-7,k8-15),(m8-15,k8-15)
    const uint32_t a_base = sb +
        (uint32_t)((wm + ((lane >> 3) & 1) * 8 + (lane & 7)) * 80 +
                   ((lane >> 4) & 1) * 16);
    // B frag base: matrices (n0-7,k0-7),(n0-7,k8-15),(n8-15,k0-7),(n8-15,k8-15)
    const uint32_t b_base = sb + A_HALVES * 2 +
        (uint32_t)((wn + ((lane >> 4) & 1) * 8 + (lane & 7)) * 80 +
                   ((lane >> 3) & 1) * 16);

    auto ldg_stage = [&](int s, int kt) {
        const int k0 = kt * 32;
        __half* As = smh + s * G_STAGE_H;
        __half* Bs = As + A_HALVES;
        // A: 256 rows x 4 chunks(8 halves) = 1024; 4 per thread
#pragma unroll
        for (int r = 0; r < 4; r++) {
            int i = tid + r * 256;
            int row = i >> 2, ch = i & 3;
            cp16(smem_u32(&As[row * AS_H + ch * 8]),
                 &A[(size_t)(m0 + row) * K + k0 + ch * 8]);
        }
        // B: 128 rows x 4 chunks = 512; 2 per thread
#pragma unroll
        for (int r = 0; r < 2; r++) {
            int i = tid + r * 256;
            int row = i >> 2, ch = i & 3;
            cp16(smem_u32(&Bs[row * AS_H + ch * 8]),
                 &Bt[(size_t)(n0 + row) * K + k0 + ch * 8]);
        }
        CP_COMMIT();
    };

    const int NKT = K / 32;
    ldg_stage(0, 0);
    ldg_stage(1, 1);
    ldg_stage(2, 2);

    for (int t = 0; t < NKT; t++) {
        CP_WAIT2();
        __syncthreads();

        const uint32_t soff = (uint32_t)((t % 3) * G_STAGE_H * 2);
#pragma unroll
        for (int ks = 0; ks < 2; ks++) {
            uint32_t a[4][4];
#pragma unroll
            for (int mi = 0; mi < 4; mi++)
                ldsm4(a[mi], a_base + soff + mi * (16 * 80) + ks * 32);
            uint32_t bf[4][4];
#pragma unroll
            for (int np = 0; np < 4; np++)
                ldsm4(bf[np], b_base + soff + np * (16 * 80) + ks * 32);
#pragma unroll
            for (int np = 0; np < 4; np++)
#pragma unroll
                for (int mi = 0; mi < 4; mi++) {
                    mma_fp16(c[mi][2 * np + 0], a[mi], &bf[np][0]);
                    mma_fp16(c[mi][2 * np + 1], a[mi], &bf[np][2]);
                }
        }
        __syncthreads();
        if (t + 3 < NKT) ldg_stage(t % 3, t + 3);
        else CP_COMMIT();
    }

    const int lg = lane >> 2, lt = lane & 3;
#pragma unroll
    for (int mi = 0; mi < 4; mi++) {
        int row = m0 + wm + mi * 16 + lg;
#pragma unroll
        for (int ni = 0; ni < 8; ni++) {
            int col = n0 + wn + ni * 8 + 2 * lt;
            float2 bv = *(const float2*)&bias[col];
            float v00 = c[mi][ni][0] + bv.x, v01 = c[mi][ni][1] + bv.y;
            float v10 = c[mi][ni][2] + bv.x, v11 = c[mi][ni][3] + bv.y;
            if (sizeof(OT) == 2) {
                *(uint32_t*)&C[(size_t)row * N + col] = packh2(v00, v01);
                *(uint32_t*)&C[(size_t)(row + 8) * N + col] = packh2(v10, v11);
            } else {
                *(float2*)&C[(size_t)row * N + col] = make_float2(v00, v01);
                *(float2*)&C[(size_t)(row + 8) * N + col] = make_float2(v10, v11);
            }
        }
    }
}

// ---------------------------------------------------------------------------
// Flash attention, fp16 mma. Br=128, Bc=64, 3-stage cp.async,
// ldmatrix for Q/K/V, P packed in-lane (no shuffles). V from vt [bh][d][n].
// ---------------------------------------------------------------------------
#define TSH 72                                // halves per tile row (64 + 8)
#define AT_KH (64 * TSH)                      // 4608 halves
#define AT_STAGE_H (2 * AT_KH)                // K + V
#define Q_OFF_H (AT_STAGE_H * 3)
#define ATTN_SMEM_BYTES ((Q_OFF_H + 128 * TSH) * 2)   // 73728 B

__global__ __launch_bounds__(256, 1)
void attn_fp16_kernel(const __half* __restrict__ qkv, const __half* __restrict__ vt,
                      __half* __restrict__ out) {
    extern __shared__ __half smh[];

    const int tid  = threadIdx.x;
    const int lane = tid & 31;
    const int warp = tid >> 5;
    const int lg = lane >> 2;
    const int lt = lane & 3;
    const int bh = blockIdx.y;
    const int b  = bh >> 4;
    const int h  = bh & 15;
    const int q0 = blockIdx.x * 128;
    const unsigned FULL = 0xffffffffu;

    const size_t base  = (size_t)b * SEQ * 3 * EMB + (size_t)h * HDIM;
    const size_t vbase = (size_t)bh * 64 * SEQ;

    auto ldg_stage = [&](int s, int it) {
        const int c0 = it * 64;
        __half* Ks = smh + s * AT_STAGE_H;
        __half* Vs = Ks + AT_KH;
        // K: 64 rows x 8 chunks = 512 -> 2/thread; V same
#pragma unroll
        for (int r = 0; r < 2; r++) {
            int i = tid + r * 256;
            int row = i >> 3, ch = i & 7;
            cp16(smem_u32(&Ks[row * TSH + ch * 8]),
                 &qkv[base + (size_t)(c0 + row) * 3072 + EMB + ch * 8]);
            cp16(smem_u32(&Vs[row * TSH + ch * 8]),
                 &vt[vbase + (size_t)row * SEQ + c0 + ch * 8]);
        }
        CP_COMMIT();
    };

    {
        __half* Qs = smh + Q_OFF_H;
#pragma unroll
        for (int r = 0; r < 4; r++) {
            int i = tid + r * 256;
            int row = i >> 3, ch = i & 7;
            cp16(smem_u32(&Qs[row * TSH + ch * 8]),
                 &qkv[base + (size_t)(q0 + row) * 3072 + ch * 8]);
        }
        CP_COMMIT();
    }
    ldg_stage(0, 0);
    ldg_stage(1, 1);
    ldg_stage(2, 2);

    CP_WAIT3();
    __syncthreads();

    const uint32_t sb = smem_u32(smh);
    const uint32_t q_base = sb + Q_OFF_H * 2 +
        (uint32_t)((warp * 16 + ((lane >> 3) & 1) * 8 + (lane & 7)) * 144 +
                   ((lane >> 4) & 1) * 16);
    const uint32_t kv_off =
        (uint32_t)((((lane >> 4) & 1) * 8 + (lane & 7)) * 144 +
                   ((lane >> 3) & 1) * 16);
    const uint32_t k_base = sb + kv_off;
    const uint32_t v_base = sb + AT_KH * 2 + kv_off;

    uint32_t aq[4][4];
#pragma unroll
    for (int kd = 0; kd < 4; kd++)
        ldsm4(aq[kd], q_base + kd * 32);

    float o[8][4];
#pragma unroll
    for (int ni = 0; ni < 8; ni++)
#pragma unroll
        for (int j = 0; j < 4; j++) o[ni][j] = 0.0f;
    float m0r = -INFINITY, m1r = -INFINITY, l0 = 0.0f, l1 = 0.0f;
    const float scale = 0.03125f;  // EMB^-0.5 (reference scales by full C)

    const int NIT = SEQ / 64;

    for (int t = 0; t < NIT; t++) {
        CP_WAIT2();
        __syncthreads();

        const uint32_t soff = (uint32_t)((t % 3) * AT_STAGE_H * 2);

        // ---- S = Q K^T ----
        float s[8][4];
#pragma unroll
        for (int ni = 0; ni < 8; ni++)
#pragma unroll
            for (int j = 0; j < 4; j++) s[ni][j] = 0.0f;
#pragma unroll
        for (int kd = 0; kd < 4; kd++) {
            uint32_t bk[4][4];
#pragma unroll
            for (int np = 0; np < 4; np++)
                ldsm4(bk[np], k_base + soff + np * (16 * 144) + kd * 32);
#pragma unroll
            for (int np = 0; np < 4; np++) {
                mma_fp16(s[2 * np + 0], aq[kd], &bk[np][0]);
                mma_fp16(s[2 * np + 1], aq[kd], &bk[np][2]);
            }
        }

        // ---- online softmax ----
        float mr0 = -INFINITY, mr1 = -INFINITY;
#pragma unroll
        for (int ni = 0; ni < 8; ni++) {
            mr0 = fmaxf(mr0, fmaxf(s[ni][0], s[ni][1]));
            mr1 = fmaxf(mr1, fmaxf(s[ni][2], s[ni][3]));
        }
#pragma unroll
        for (int off = 1; off <= 2; off <<= 1) {
            mr0 = fmaxf(mr0, __shfl_xor_sync(FULL, mr0, off));
            mr1 = fmaxf(mr1, __shfl_xor_sync(FULL, mr1, off));
        }
        float mn0 = fmaxf(m0r, mr0 * scale);
        float mn1 = fmaxf(m1r, mr1 * scale);
        float f0 = __expf(m0r - mn0);
        float f1 = __expf(m1r - mn1);
        m0r = mn0; m1r = mn1;

        float rs0 = 0.0f, rs1 = 0.0f;
#pragma unroll
        for (int ni = 0; ni < 8; ni++) {
            float p0 = __expf(s[ni][0] * scale - mn0);
            float p1 = __expf(s[ni][1] * scale - mn0);
            float p2 = __expf(s[ni][2] * scale - mn1);
            float p3 = __expf(s[ni][3] * scale - mn1);
            rs0 += p0 + p1;
            rs1 += p2 + p3;
            s[ni][0] = p0; s[ni][1] = p1;
            s[ni][2] = p2; s[ni][3] = p3;
            o[ni][0] *= f0; o[ni][1] *= f0;
            o[ni][2] *= f1; o[ni][3] *= f1;
        }
#pragma unroll
        for (int off = 1; off <= 2; off <<= 1) {
            rs0 += __shfl_xor_sync(FULL, rs0, off);
            rs1 += __shfl_xor_sync(FULL, rs1, off);
        }
        l0 = l0 * f0 + rs0;
        l1 = l1 * f1 + rs1;

        // ---- O += P V  (P a-frags packed in-lane; V b-frags via ldmatrix) ----
#pragma unroll
        for (int kk = 0; kk < 4; kk++) {
            uint32_t pa[4];
            pa[0] = packh2(s[2 * kk][0], s[2 * kk][1]);
            pa[1] = packh2(s[2 * kk][2], s[2 * kk][3]);
            pa[2] = packh2(s[2 * kk + 1][0], s[2 * kk + 1][1]);
            pa[3] = packh2(s[2 * kk + 1][2], s[2 * kk + 1][3]);
            uint32_t bv[4][4];
#pragma unroll
            for (int np = 0; np < 4; np++)
                ldsm4(bv[np], v_base + soff + np * (16 * 144) + kk * 32);
#pragma unroll
            for (int np = 0; np < 4; np++) {
                mma_fp16(o[2 * np + 0], pa, &bv[np][0]);
                mma_fp16(o[2 * np + 1], pa, &bv[np][2]);
            }
        }
        __syncthreads();
        if (t + 3 < NIT) ldg_stage(t % 3, t + 3);
        else CP_COMMIT();
    }

    // ---- normalize, write fp16 [B,N,C] ----
    float inv0 = 1.0f / l0, inv1 = 1.0f / l1;
    int r = q0 + warp * 16 + lg;
#pragma unroll
    for (int ni = 0; ni < 8; ni++) {
        int col = h * HDIM + ni * 8 + 2 * lt;
        *(uint32_t*)&out[((size_t)b * SEQ + r) * EMB + col] =
            packh2(o[ni][0] * inv0, o[ni][1] * inv0);
        *(uint32_t*)&out[((size_t)b * SEQ + r + 8) * EMB + col] =
            packh2(o[ni][2] * inv1, o[ni][3] * inv1);
    }
}

// ---------------------------------------------------------------------------
extern "C" void kernel_launch(void* const* d_in, const int* in_sizes, int n_in,
                              void* d_out, int out_size) {
    const float* x     = (const float*)d_in[0];
    const float* W_qkv = (const float*)d_in[1];
    const float* b_qkv = (const float*)d_in[2];
    const float* W_out = (const float*)d_in[3];
    const float* b_out = (const float*)d_in[4];
    float* out = (float*)d_out;

    __half *qkv, *attn, *xh, *wqkvt, *woutt, *vt;
    cudaGetSymbolAddress((void**)&qkv, g_qkv);
    cudaGetSymbolAddress((void**)&attn, g_attn);
    cudaGetSymbolAddress((void**)&xh, g_xh);
    cudaGetSymbolAddress((void**)&wqkvt, g_wqkvt);
    cudaGetSymbolAddress((void**)&woutt, g_woutt);
    cudaGetSymbolAddress((void**)&vt, g_vt);

    cudaFuncSetAttribute(gemm_fp16_kernel<__half>,
                         cudaFuncAttributeMaxDynamicSharedMemorySize,
                         GEMM_SMEM_BYTES);
    cudaFuncSetAttribute(gemm_fp16_kernel<float>,
                         cudaFuncAttributeMaxDynamicSharedMemorySize,
                         GEMM_SMEM_BYTES);
    cudaFuncSetAttribute(attn_fp16_kernel,
                         cudaFuncAttributeMaxDynamicSharedMemorySize,
                         ATTN_SMEM_BYTES);

    // 0) prep: x -> fp16; weights -> transposed fp16 [N,K]
    {
        int n4 = M_TOT * EMB / 4;
        cvt_h_kernel<<<(n4 + 255) / 256, 256>>>((const float4*)x, (uint2*)xh, n4);
        transpose_h_kernel<<<dim3(QKV_N / 32, EMB / 32), dim3(32, 8)>>>(
            W_qkv, wqkvt, EMB, QKV_N);
        transpose_h_kernel<<<dim3(EMB / 32, EMB / 32), dim3(32, 8)>>>(
            W_out, woutt, EMB, EMB);
    }

    // 1) QKV projection -> fp16 qkv
    gemm_fp16_kernel<__half><<<dim3(QKV_N / 128, M_TOT / 256), 256,
                               GEMM_SMEM_BYTES>>>(
        xh, wqkvt, b_qkv, qkv, M_TOT, QKV_N, EMB);
    // 1b) transpose V for ldmatrix-friendly PV
    transpose_v_kernel<<<dim3(SEQ / 32, HDIM / 32, BATCH * HEADS), dim3(32, 8)>>>(
        qkv, vt);
    // 2) Attention -> fp16 attn
    attn_fp16_kernel<<<dim3(SEQ / 128, BATCH * HEADS), 256, ATTN_SMEM_BYTES>>>(
        qkv, vt, attn);
    // 3) Output projection -> fp32 out
    gemm_fp16_kernel<float><<<dim3(EMB / 128, M_TOT / 256), 256,
                              GEMM_SMEM_BYTES>>>(
        attn, woutt, b_out, out, M_TOT, EMB, EMB);
}

// round 9
// speedup vs baseline: 1.9220x; 1.0278x over previous
#include <cuda_runtime.h>
#include <cuda_fp16.h>
#include <math.h>
#include <stdint.h>

#define BATCH 2
#define SEQ   2048
#define EMB   1024
#define HEADS 16
#define HDIM  64
#define M_TOT (BATCH * SEQ)   // 4096
#define QKV_N (3 * EMB)       // 3072

__device__ __half g_qkv[M_TOT * QKV_N];     // [B,N,3,H,D] fp16
__device__ __half g_attn[M_TOT * EMB];      // [B,N,C] fp16
__device__ __half g_xh[M_TOT * EMB];        // x fp16
__device__ __half g_wqkvt[QKV_N * EMB];     // W_qkv^T [N,K] fp16
__device__ __half g_woutt[EMB * EMB];       // W_out^T [N,K] fp16
__device__ __half g_vt[M_TOT * EMB];        // V transposed [B,H,D,SEQ] fp16

// ---------------------------------------------------------------------------
// helpers
// ---------------------------------------------------------------------------
__device__ __forceinline__ void mma_fp16(float* c, const uint32_t* a,
                                         const uint32_t* b) {
    asm volatile(
        "mma.sync.aligned.m16n8k16.row.col.f32.f16.f16.f32 "
        "{%0,%1,%2,%3},{%4,%5,%6,%7},{%8,%9},{%0,%1,%2,%3};"
        : "+f"(c[0]), "+f"(c[1]), "+f"(c[2]), "+f"(c[3])
        : "r"(a[0]), "r"(a[1]), "r"(a[2]), "r"(a[3]), "r"(b[0]), "r"(b[1]));
}
__device__ __forceinline__ void ldsm4(uint32_t* u, uint32_t saddr) {
    asm volatile(
        "ldmatrix.sync.aligned.m8n8.x4.shared.b16 {%0,%1,%2,%3}, [%4];"
        : "=r"(u[0]), "=r"(u[1]), "=r"(u[2]), "=r"(u[3]) : "r"(saddr));
}
__device__ __forceinline__ uint32_t smem_u32(const void* p) {
    return (uint32_t)__cvta_generic_to_shared(p);
}
__device__ __forceinline__ void cp16(uint32_t s, const void* g) {
    asm volatile("cp.async.cg.shared.global [%0], [%1], 16;" :: "r"(s), "l"(g));
}
#define CP_COMMIT() asm volatile("cp.async.commit_group;")
#define CP_WAIT2()  asm volatile("cp.async.wait_group 2;")
#define CP_WAIT3()  asm volatile("cp.async.wait_group 3;")
__device__ __forceinline__ uint32_t packh2(float lo, float hi) {
    __half2 h = __floats2half2_rn(lo, hi);
    return *(uint32_t*)&h;
}

// ---------------------------------------------------------------------------
// prep kernels
// ---------------------------------------------------------------------------
__global__ void cvt_h_kernel(const float4* __restrict__ in,
                             uint2* __restrict__ out, int n4) {
    int i = blockIdx.x * blockDim.x + threadIdx.x;
    if (i < n4) {
        float4 v = in[i];
        uint2 o;
        o.x = packh2(v.x, v.y);
        o.y = packh2(v.z, v.w);
        out[i] = o;
    }
}

// out[n][k] = half(in[k][n]);  in: [K,N] fp32 row-major -> out: [N,K] fp16
__global__ void transpose_h_kernel(const float* __restrict__ in,
                                   __half* __restrict__ out, int K, int N) {
    __shared__ float t[32][33];
    int n0 = blockIdx.x * 32, k0 = blockIdx.y * 32;
    int tx = threadIdx.x, ty = threadIdx.y;   // 32 x 8
#pragma unroll
    for (int j = 0; j < 32; j += 8)
        t[ty + j][tx] = in[(size_t)(k0 + ty + j) * N + n0 + tx];
    __syncthreads();
#pragma unroll
    for (int j = 0; j < 32; j += 8)
        out[(size_t)(n0 + ty + j) * K + k0 + tx] = __float2half_rn(t[tx][ty + j]);
}

// vt[bh][d][n] = qkv V-part (fp16 passthrough)
__global__ void transpose_v_kernel(const __half* __restrict__ qkv,
                                   __half* __restrict__ vt) {
    __shared__ __half t[32][34];
    int n0 = blockIdx.x * 32, d0 = blockIdx.y * 32;
    int bh = blockIdx.z;
    int b = bh >> 4, h = bh & 15;
    int tx = threadIdx.x, ty = threadIdx.y;
    const size_t inbase = (size_t)b * SEQ * 3072 + 2048 + (size_t)h * 64;
#pragma unroll
    for (int j = 0; j < 32; j += 8)
        t[ty + j][tx] = qkv[inbase + (size_t)(n0 + ty + j) * 3072 + d0 + tx];
    __syncthreads();
    const size_t outbase = (size_t)bh * 64 * SEQ;
#pragma unroll
    for (int j = 0; j < 32; j += 8)
        vt[outbase + (size_t)(d0 + ty + j) * SEQ + n0 + tx] = t[tx][ty + j];
}

// ---------------------------------------------------------------------------
// FP16 GEMM: C[M,N] = A[M,K] @ Bt[N,K]^T + bias
// Block 128x128 (2 CTAs/SM for cross-CTA latency hiding), 8 warps (2Mx4N),
// warp tile 64x32, K-tile 32, 3-stage cp.async, ldmatrix, mma.m16n8k16.
// ---------------------------------------------------------------------------
#define AS_H 40                                   // halves per row (32 + 8 pad)
#define A_HALVES (128 * AS_H)                     // 5120
#define B_HALVES (128 * AS_H)                     // 5120
#define G_STAGE_H (A_HALVES + B_HALVES)           // 10240 halves
#define GEMM_SMEM_BYTES (G_STAGE_H * 3 * 2)       // 61440 B

template <typename OT>
__global__ __launch_bounds__(256, 2)
void gemm_fp16_kernel(const __half* __restrict__ A, const __half* __restrict__ Bt,
                      const float* __restrict__ bias, OT* __restrict__ C,
                      int M, int N, int K) {
    extern __shared__ __half smh[];

    const int tid  = threadIdx.x;
    const int lane = tid & 31;
    const int warp = tid >> 5;
    const int wm = (warp >> 2) * 64;   // 0,64
    const int wn = (warp & 3) * 32;    // 0,32,64,96
    const int m0 = blockIdx.y * 128;
    const int n0 = blockIdx.x * 128;

    float c[4][4][4];
#pragma unroll
    for (int mi = 0; mi < 4; mi++)
#pragma unroll
        for (int ni = 0; ni < 4; ni++)
#pragma unroll
            for (int j = 0; j < 4; j++) c[mi][ni][j] = 0.0f;

    const uint32_t sb = smem_u32(smh);
    // A frag base: matrices (m,kl),(m+8,kl),(m,kh),(m+8,kh)
    const uint32_t a_base = sb +
        (uint32_t)((wm + ((lane >> 3) & 1) * 8 + (lane & 7)) * 80 +
                   ((lane >> 4) & 1) * 16);
    // B frag base: matrices (n,kl),(n,kh),(n+8,kl),(n+8,kh)
    const uint32_t b_base = sb + A_HALVES * 2 +
        (uint32_t)((wn + ((lane >> 4) & 1) * 8 + (lane & 7)) * 80 +
                   ((lane >> 3) & 1) * 16);

    auto ldg_stage = [&](int s, int kt) {
        const int k0 = kt * 32;
        __half* As = smh + s * G_STAGE_H;
        __half* Bs = As + A_HALVES;
        // A: 128 rows x 4 chunks(8h) = 512 -> 2/thread; B same
#pragma unroll
        for (int r = 0; r < 2; r++) {
            int i = tid + r * 256;
            int row = i >> 2, ch = i & 3;
            cp16(smem_u32(&As[row * AS_H + ch * 8]),
                 &A[(size_t)(m0 + row) * K + k0 + ch * 8]);
            cp16(smem_u32(&Bs[row * AS_H + ch * 8]),
                 &Bt[(size_t)(n0 + row) * K + k0 + ch * 8]);
        }
        CP_COMMIT();
    };

    const int NKT = K / 32;
    ldg_stage(0, 0);
    ldg_stage(1, 1);
    ldg_stage(2, 2);

    for (int t = 0; t < NKT; t++) {
        CP_WAIT2();
        __syncthreads();

        const uint32_t soff = (uint32_t)((t % 3) * G_STAGE_H * 2);
#pragma unroll
        for (int ks = 0; ks < 2; ks++) {
            uint32_t a[4][4];
#pragma unroll
            for (int mi = 0; mi < 4; mi++)
                ldsm4(a[mi], a_base + soff + mi * (16 * 80) + ks * 32);
            uint32_t bf[2][4];
#pragma unroll
            for (int np = 0; np < 2; np++)
                ldsm4(bf[np], b_base + soff + np * (16 * 80) + ks * 32);
#pragma unroll
            for (int np = 0; np < 2; np++)
#pragma unroll
                for (int mi = 0; mi < 4; mi++) {
                    mma_fp16(c[mi][2 * np + 0], a[mi], &bf[np][0]);
                    mma_fp16(c[mi][2 * np + 1], a[mi], &bf[np][2]);
                }
        }
        __syncthreads();
        if (t + 3 < NKT) ldg_stage(t % 3, t + 3);
        else CP_COMMIT();
    }

    const int lg = lane >> 2, lt = lane & 3;
#pragma unroll
    for (int mi = 0; mi < 4; mi++) {
        int row = m0 + wm + mi * 16 + lg;
#pragma unroll
        for (int ni = 0; ni < 4; ni++) {
            int col = n0 + wn + ni * 8 + 2 * lt;
            float2 bv = *(const float2*)&bias[col];
            float v00 = c[mi][ni][0] + bv.x, v01 = c[mi][ni][1] + bv.y;
            float v10 = c[mi][ni][2] + bv.x, v11 = c[mi][ni][3] + bv.y;
            if (sizeof(OT) == 2) {
                *(uint32_t*)&C[(size_t)row * N + col] = packh2(v00, v01);
                *(uint32_t*)&C[(size_t)(row + 8) * N + col] = packh2(v10, v11);
            } else {
                *(float2*)&C[(size_t)row * N + col] = make_float2(v00, v01);
                *(float2*)&C[(size_t)(row + 8) * N + col] = make_float2(v10, v11);
            }
        }
    }
}

// ---------------------------------------------------------------------------
// Flash attention, fp16 mma (unchanged from R8). Br=128, Bc=64,
// 3-stage cp.async, ldmatrix Q/K/V, P packed in-lane. V from vt [bh][d][n].
// ---------------------------------------------------------------------------
#define TSH 72                                // halves per tile row (64 + 8)
#define AT_KH (64 * TSH)                      // 4608 halves
#define AT_STAGE_H (2 * AT_KH)                // K + V
#define Q_OFF_H (AT_STAGE_H * 3)
#define ATTN_SMEM_BYTES ((Q_OFF_H + 128 * TSH) * 2)   // 73728 B

__global__ __launch_bounds__(256, 1)
void attn_fp16_kernel(const __half* __restrict__ qkv, const __half* __restrict__ vt,
                      __half* __restrict__ out) {
    extern __shared__ __half smh[];

    const int tid  = threadIdx.x;
    const int lane = tid & 31;
    const int warp = tid >> 5;
    const int lg = lane >> 2;
    const int lt = lane & 3;
    const int bh = blockIdx.y;
    const int b  = bh >> 4;
    const int h  = bh & 15;
    const int q0 = blockIdx.x * 128;
    const unsigned FULL = 0xffffffffu;

    const size_t base  = (size_t)b * SEQ * 3 * EMB + (size_t)h * HDIM;
    const size_t vbase = (size_t)bh * 64 * SEQ;

    auto ldg_stage = [&](int s, int it) {
        const int c0 = it * 64;
        __half* Ks = smh + s * AT_STAGE_H;
        __half* Vs = Ks + AT_KH;
#pragma unroll
        for (int r = 0; r < 2; r++) {
            int i = tid + r * 256;
            int row = i >> 3, ch = i & 7;
            cp16(smem_u32(&Ks[row * TSH + ch * 8]),
                 &qkv[base + (size_t)(c0 + row) * 3072 + EMB + ch * 8]);
            cp16(smem_u32(&Vs[row * TSH + ch * 8]),
                 &vt[vbase + (size_t)row * SEQ + c0 + ch * 8]);
        }
        CP_COMMIT();
    };

    {
        __half* Qs = smh + Q_OFF_H;
#pragma unroll
        for (int r = 0; r < 4; r++) {
            int i = tid + r * 256;
            int row = i >> 3, ch = i & 7;
            cp16(smem_u32(&Qs[row * TSH + ch * 8]),
                 &qkv[base + (size_t)(q0 + row) * 3072 + ch * 8]);
        }
        CP_COMMIT();
    }
    ldg_stage(0, 0);
    ldg_stage(1, 1);
    ldg_stage(2, 2);

    CP_WAIT3();
    __syncthreads();

    const uint32_t sb = smem_u32(smh);
    const uint32_t q_base = sb + Q_OFF_H * 2 +
        (uint32_t)((warp * 16 + ((lane >> 3) & 1) * 8 + (lane & 7)) * 144 +
                   ((lane >> 4) & 1) * 16);
    const uint32_t kv_off =
        (uint32_t)((((lane >> 4) & 1) * 8 + (lane & 7)) * 144 +
                   ((lane >> 3) & 1) * 16);
    const uint32_t k_base = sb + kv_off;
    const uint32_t v_base = sb + AT_KH * 2 + kv_off;

    uint32_t aq[4][4];
#pragma unroll
    for (int kd = 0; kd < 4; kd++)
        ldsm4(aq[kd], q_base + kd * 32);

    float o[8][4];
#pragma unroll
    for (int ni = 0; ni < 8; ni++)
#pragma unroll
        for (int j = 0; j < 4; j++) o[ni][j] = 0.0f;
    float m0r = -INFINITY, m1r = -INFINITY, l0 = 0.0f, l1 = 0.0f;
    const float scale = 0.03125f;  // EMB^-0.5 (reference scales by full C)

    const int NIT = SEQ / 64;

    for (int t = 0; t < NIT; t++) {
        CP_WAIT2();
        __syncthreads();

        const uint32_t soff = (uint32_t)((t % 3) * AT_STAGE_H * 2);

        // ---- S = Q K^T ----
        float s[8][4];
#pragma unroll
        for (int ni = 0; ni < 8; ni++)
#pragma unroll
            for (int j = 0; j < 4; j++) s[ni][j] = 0.0f;
#pragma unroll
        for (int kd = 0; kd < 4; kd++) {
            uint32_t bk[4][4];
#pragma unroll
            for (int np = 0; np < 4; np++)
                ldsm4(bk[np], k_base + soff + np * (16 * 144) + kd * 32);
#pragma unroll
            for (int np = 0; np < 4; np++) {
                mma_fp16(s[2 * np + 0], aq[kd], &bk[np][0]);
                mma_fp16(s[2 * np + 1], aq[kd], &bk[np][2]);
            }
        }

        // ---- online softmax ----
        float mr0 = -INFINITY, mr1 = -INFINITY;
#pragma unroll
        for (int ni = 0; ni < 8; ni++) {
            mr0 = fmaxf(mr0, fmaxf(s[ni][0], s[ni][1]));
            mr1 = fmaxf(mr1, fmaxf(s[ni][2], s[ni][3]));
        }
#pragma unroll
        for (int off = 1; off <= 2; off <<= 1) {
            mr0 = fmaxf(mr0, __shfl_xor_sync(FULL, mr0, off));
            mr1 = fmaxf(mr1, __shfl_xor_sync(FULL, mr1, off));
        }
        float mn0 = fmaxf(m0r, mr0 * scale);
        float mn1 = fmaxf(m1r, mr1 * scale);
        float f0 = __expf(m0r - mn0);
        float f1 = __expf(m1r - mn1);
        m0r = mn0; m1r = mn1;

        float rs0 = 0.0f, rs1 = 0.0f;
#pragma unroll
        for (int ni = 0; ni < 8; ni++) {
            float p0 = __expf(s[ni][0] * scale - mn0);
            float p1 = __expf(s[ni][1] * scale - mn0);
            float p2 = __expf(s[ni][2] * scale - mn1);
            float p3 = __expf(s[ni][3] * scale - mn1);
            rs0 += p0 + p1;
            rs1 += p2 + p3;
            s[ni][0] = p0; s[ni][1] = p1;
            s[ni][2] = p2; s[ni][3] = p3;
            o[ni][0] *= f0; o[ni][1] *= f0;
            o[ni][2] *= f1; o[ni][3] *= f1;
        }
#pragma unroll
        for (int off = 1; off <= 2; off <<= 1) {
            rs0 += __shfl_xor_sync(FULL, rs0, off);
            rs1 += __shfl_xor_sync(FULL, rs1, off);
        }
        l0 = l0 * f0 + rs0;
        l1 = l1 * f1 + rs1;

        // ---- O += P V ----
#pragma unroll
        for (int kk = 0; kk < 4; kk++) {
            uint32_t pa[4];
            pa[0] = packh2(s[2 * kk][0], s[2 * kk][1]);
            pa[1] = packh2(s[2 * kk][2], s[2 * kk][3]);
            pa[2] = packh2(s[2 * kk + 1][0], s[2 * kk + 1][1]);
            pa[3] = packh2(s[2 * kk + 1][2], s[2 * kk + 1][3]);
            uint32_t bv[4][4];
#pragma unroll
            for (int np = 0; np < 4; np++)
                ldsm4(bv[np], v_base + soff + np * (16 * 144) + kk * 32);
#pragma unroll
            for (int np = 0; np < 4; np++) {
                mma_fp16(o[2 * np + 0], pa, &bv[np][0]);
                mma_fp16(o[2 * np + 1], pa, &bv[np][2]);
            }
        }
        __syncthreads();
        if (t + 3 < NIT) ldg_stage(t % 3, t + 3);
        else CP_COMMIT();
    }

    // ---- normalize, write fp16 [B,N,C] ----
    float inv0 = 1.0f / l0, inv1 = 1.0f / l1;
    int r = q0 + warp * 16 + lg;
#pragma unroll
    for (int ni = 0; ni < 8; ni++) {
        int col = h * HDIM + ni * 8 + 2 * lt;
        *(uint32_t*)&out[((size_t)b * SEQ + r) * EMB + col] =
            packh2(o[ni][0] * inv0, o[ni][1] * inv0);
        *(uint32_t*)&out[((size_t)b * SEQ + r + 8) * EMB + col] =
            packh2(o[ni][2] * inv1, o[ni][3] * inv1);
    }
}

// ---------------------------------------------------------------------------
extern "C" void kernel_launch(void* const* d_in, const int* in_sizes, int n_in,
                              void* d_out, int out_size) {
    const float* x     = (const float*)d_in[0];
    const float* W_qkv = (const float*)d_in[1];
    const float* b_qkv = (const float*)d_in[2];
    const float* W_out = (const float*)d_in[3];
    const float* b_out = (const float*)d_in[4];
    float* out = (float*)d_out;

    __half *qkv, *attn, *xh, *wqkvt, *woutt, *vt;
    cudaGetSymbolAddress((void**)&qkv, g_qkv);
    cudaGetSymbolAddress((void**)&attn, g_attn);
    cudaGetSymbolAddress((void**)&xh, g_xh);
    cudaGetSymbolAddress((void**)&wqkvt, g_wqkvt);
    cudaGetSymbolAddress((void**)&woutt, g_woutt);
    cudaGetSymbolAddress((void**)&vt, g_vt);

    cudaFuncSetAttribute(gemm_fp16_kernel<__half>,
                         cudaFuncAttributeMaxDynamicSharedMemorySize,
                         GEMM_SMEM_BYTES);
    cudaFuncSetAttribute(gemm_fp16_kernel<float>,
                         cudaFuncAttributeMaxDynamicSharedMemorySize,
                         GEMM_SMEM_BYTES);
    cudaFuncSetAttribute(attn_fp16_kernel,
                         cudaFuncAttributeMaxDynamicSharedMemorySize,
                         ATTN_SMEM_BYTES);

    // 0) prep: x -> fp16; weights -> transposed fp16 [N,K]
    {
        int n4 = M_TOT * EMB / 4;
        cvt_h_kernel<<<(n4 + 255) / 256, 256>>>((const float4*)x, (uint2*)xh, n4);
        transpose_h_kernel<<<dim3(QKV_N / 32, EMB / 32), dim3(32, 8)>>>(
            W_qkv, wqkvt, EMB, QKV_N);
        transpose_h_kernel<<<dim3(EMB / 32, EMB / 32), dim3(32, 8)>>>(
            W_out, woutt, EMB, EMB);
    }

    // 1) QKV projection -> fp16 qkv
    gemm_fp16_kernel<__half><<<dim3(QKV_N / 128, M_TOT / 128), 256,
                               GEMM_SMEM_BYTES>>>(
        xh, wqkvt, b_qkv, qkv, M_TOT, QKV_N, EMB);
    // 1b) transpose V for ldmatrix-friendly PV
    transpose_v_kernel<<<dim3(SEQ / 32, HDIM / 32, BATCH * HEADS), dim3(32, 8)>>>(
        qkv, vt);
    // 2) Attention -> fp16 attn
    attn_fp16_kernel<<<dim3(SEQ / 128, BATCH * HEADS), 256, ATTN_SMEM_BYTES>>>(
        qkv, vt, attn);
    // 3) Output projection -> fp32 out
    gemm_fp16_kernel<float><<<dim3(EMB / 128, M_TOT / 128), 256,
                              GEMM_SMEM_BYTES>>>(
        attn, woutt, b_out, out, M_TOT, EMB, EMB);
}

// round 10
// speedup vs baseline: 2.0325x; 1.0575x over previous
#include <cuda_runtime.h>
#include <cuda_fp16.h>
#include <math.h>
#include <stdint.h>

#define BATCH 2
#define SEQ   2048
#define EMB   1024
#define HEADS 16
#define HDIM  64
#define M_TOT (BATCH * SEQ)   // 4096
#define QKV_N (3 * EMB)       // 3072

__device__ __half g_qkv[M_TOT * QKV_N];     // [B,N,3,H,D] fp16
__device__ __half g_attn[M_TOT * EMB];      // [B,N,C] fp16
__device__ __half g_xh[M_TOT * EMB];        // x fp16
__device__ __half g_wqkvt[QKV_N * EMB];     // W_qkv^T [N,K] fp16
__device__ __half g_woutt[EMB * EMB];       // W_out^T [N,K] fp16
__device__ __half g_vt[M_TOT * EMB];        // V transposed [B,H,D,SEQ] fp16

// ---------------------------------------------------------------------------
// helpers
// ---------------------------------------------------------------------------
__device__ __forceinline__ void mma_fp16(float* c, const uint32_t* a,
                                         const uint32_t* b) {
    asm volatile(
        "mma.sync.aligned.m16n8k16.row.col.f32.f16.f16.f32 "
        "{%0,%1,%2,%3},{%4,%5,%6,%7},{%8,%9},{%0,%1,%2,%3};"
        : "+f"(c[0]), "+f"(c[1]), "+f"(c[2]), "+f"(c[3])
        : "r"(a[0]), "r"(a[1]), "r"(a[2]), "r"(a[3]), "r"(b[0]), "r"(b[1]));
}
__device__ __forceinline__ void ldsm4(uint32_t* u, uint32_t saddr) {
    asm volatile(
        "ldmatrix.sync.aligned.m8n8.x4.shared.b16 {%0,%1,%2,%3}, [%4];"
        : "=r"(u[0]), "=r"(u[1]), "=r"(u[2]), "=r"(u[3]) : "r"(saddr));
}
__device__ __forceinline__ uint32_t smem_u32(const void* p) {
    return (uint32_t)__cvta_generic_to_shared(p);
}
__device__ __forceinline__ void cp16(uint32_t s, const void* g) {
    asm volatile("cp.async.cg.shared.global [%0], [%1], 16;" :: "r"(s), "l"(g));
}
#define CP_COMMIT() asm volatile("cp.async.commit_group;")
#define CP_WAIT2()  asm volatile("cp.async.wait_group 2;")
#define CP_WAIT3()  asm volatile("cp.async.wait_group 3;")
__device__ __forceinline__ uint32_t packh2(float lo, float hi) {
    __half2 h = __floats2half2_rn(lo, hi);
    return *(uint32_t*)&h;
}

// ---------------------------------------------------------------------------
// prep kernels
// ---------------------------------------------------------------------------
__global__ void cvt_h_kernel(const float4* __restrict__ in,
                             uint2* __restrict__ out, int n4) {
    int i = blockIdx.x * blockDim.x + threadIdx.x;
    if (i < n4) {
        float4 v = in[i];
        uint2 o;
        o.x = packh2(v.x, v.y);
        o.y = packh2(v.z, v.w);
        out[i] = o;
    }
}

// out[n][k] = half(in[k][n]);  in: [K,N] fp32 row-major -> out: [N,K] fp16
__global__ void transpose_h_kernel(const float* __restrict__ in,
                                   __half* __restrict__ out, int K, int N) {
    __shared__ float t[32][33];
    int n0 = blockIdx.x * 32, k0 = blockIdx.y * 32;
    int tx = threadIdx.x, ty = threadIdx.y;   // 32 x 8
#pragma unroll
    for (int j = 0; j < 32; j += 8)
        t[ty + j][tx] = in[(size_t)(k0 + ty + j) * N + n0 + tx];
    __syncthreads();
#pragma unroll
    for (int j = 0; j < 32; j += 8)
        out[(size_t)(n0 + ty + j) * K + k0 + tx] = __float2half_rn(t[tx][ty + j]);
}

// vt[bh][d][n] = qkv V-part (fp16 passthrough)
__global__ void transpose_v_kernel(const __half* __restrict__ qkv,
                                   __half* __restrict__ vt) {
    __shared__ __half t[32][34];
    int n0 = blockIdx.x * 32, d0 = blockIdx.y * 32;
    int bh = blockIdx.z;
    int b = bh >> 4, h = bh & 15;
    int tx = threadIdx.x, ty = threadIdx.y;
    const size_t inbase = (size_t)b * SEQ * 3072 + 2048 + (size_t)h * 64;
#pragma unroll
    for (int j = 0; j < 32; j += 8)
        t[ty + j][tx] = qkv[inbase + (size_t)(n0 + ty + j) * 3072 + d0 + tx];
    __syncthreads();
    const size_t outbase = (size_t)bh * 64 * SEQ;
#pragma unroll
    for (int j = 0; j < 32; j += 8)
        vt[outbase + (size_t)(d0 + ty + j) * SEQ + n0 + tx] = t[tx][ty + j];
}

// ---------------------------------------------------------------------------
// FP16 GEMM: C[M,N] = A[M,K] @ Bt[N,K]^T + bias
// Block 128x128, 8 warps (2Mx4N), warp tile 64x32, K-tile 64 (64 MMAs/warp
// per barrier pair), 3-stage cp.async, ldmatrix, mma.m16n8k16. 2 CTAs/SM.
// ---------------------------------------------------------------------------
#define AS_H 72                                   // halves per row (64 + 8 pad)
#define A_HALVES (128 * AS_H)                     // 9216
#define B_HALVES (128 * AS_H)                     // 9216
#define G_STAGE_H (A_HALVES + B_HALVES)           // 18432 halves
#define GEMM_SMEM_BYTES (G_STAGE_H * 3 * 2)       // 110592 B

template <typename OT>
__global__ __launch_bounds__(256, 2)
void gemm_fp16_kernel(const __half* __restrict__ A, const __half* __restrict__ Bt,
                      const float* __restrict__ bias, OT* __restrict__ C,
                      int M, int N, int K) {
    extern __shared__ __half smh[];

    const int tid  = threadIdx.x;
    const int lane = tid & 31;
    const int warp = tid >> 5;
    const int wm = (warp >> 2) * 64;   // 0,64
    const int wn = (warp & 3) * 32;    // 0,32,64,96
    const int m0 = blockIdx.y * 128;
    const int n0 = blockIdx.x * 128;

    float c[4][4][4];
#pragma unroll
    for (int mi = 0; mi < 4; mi++)
#pragma unroll
        for (int ni = 0; ni < 4; ni++)
#pragma unroll
            for (int j = 0; j < 4; j++) c[mi][ni][j] = 0.0f;

    const uint32_t sb = smem_u32(smh);
    // A frag base: matrices (m,kl),(m+8,kl),(m,kh),(m+8,kh); row stride 144 B
    const uint32_t a_base = sb +
        (uint32_t)((wm + ((lane >> 3) & 1) * 8 + (lane & 7)) * 144 +
                   ((lane >> 4) & 1) * 16);
    // B frag base: matrices (n,kl),(n,kh),(n+8,kl),(n+8,kh)
    const uint32_t b_base = sb + A_HALVES * 2 +
        (uint32_t)((wn + ((lane >> 4) & 1) * 8 + (lane & 7)) * 144 +
                   ((lane >> 3) & 1) * 16);

    auto ldg_stage = [&](int s, int kt) {
        const int k0 = kt * 64;
        __half* As = smh + s * G_STAGE_H;
        __half* Bs = As + A_HALVES;
        // A: 128 rows x 8 chunks(8h) = 1024 -> 4/thread; B same
#pragma unroll
        for (int r = 0; r < 4; r++) {
            int i = tid + r * 256;
            int row = i >> 3, ch = i & 7;
            cp16(smem_u32(&As[row * AS_H + ch * 8]),
                 &A[(size_t)(m0 + row) * K + k0 + ch * 8]);
            cp16(smem_u32(&Bs[row * AS_H + ch * 8]),
                 &Bt[(size_t)(n0 + row) * K + k0 + ch * 8]);
        }
        CP_COMMIT();
    };

    const int NKT = K / 64;
    ldg_stage(0, 0);
    ldg_stage(1, 1);
    ldg_stage(2, 2);

    for (int t = 0; t < NKT; t++) {
        CP_WAIT2();
        __syncthreads();

        const uint32_t soff = (uint32_t)((t % 3) * G_STAGE_H * 2);
#pragma unroll
        for (int ks = 0; ks < 4; ks++) {
            uint32_t a[4][4];
#pragma unroll
            for (int mi = 0; mi < 4; mi++)
                ldsm4(a[mi], a_base + soff + mi * (16 * 144) + ks * 32);
            uint32_t bf[2][4];
#pragma unroll
            for (int np = 0; np < 2; np++)
                ldsm4(bf[np], b_base + soff + np * (16 * 144) + ks * 32);
#pragma unroll
            for (int np = 0; np < 2; np++)
#pragma unroll
                for (int mi = 0; mi < 4; mi++) {
                    mma_fp16(c[mi][2 * np + 0], a[mi], &bf[np][0]);
                    mma_fp16(c[mi][2 * np + 1], a[mi], &bf[np][2]);
                }
        }
        __syncthreads();
        if (t + 3 < NKT) ldg_stage(t % 3, t + 3);
        else CP_COMMIT();
    }

    const int lg = lane >> 2, lt = lane & 3;
#pragma unroll
    for (int mi = 0; mi < 4; mi++) {
        int row = m0 + wm + mi * 16 + lg;
#pragma unroll
        for (int ni = 0; ni < 4; ni++) {
            int col = n0 + wn + ni * 8 + 2 * lt;
            float2 bv = *(const float2*)&bias[col];
            float v00 = c[mi][ni][0] + bv.x, v01 = c[mi][ni][1] + bv.y;
            float v10 = c[mi][ni][2] + bv.x, v11 = c[mi][ni][3] + bv.y;
            if (sizeof(OT) == 2) {
                *(uint32_t*)&C[(size_t)row * N + col] = packh2(v00, v01);
                *(uint32_t*)&C[(size_t)(row + 8) * N + col] = packh2(v10, v11);
            } else {
                *(float2*)&C[(size_t)row * N + col] = make_float2(v00, v01);
                *(float2*)&C[(size_t)(row + 8) * N + col] = make_float2(v10, v11);
            }
        }
    }
}

// ---------------------------------------------------------------------------
// Flash attention, fp16 mma (unchanged from R8/R9). Br=128, Bc=64,
// 3-stage cp.async, ldmatrix Q/K/V, P packed in-lane. V from vt [bh][d][n].
// ---------------------------------------------------------------------------
#define TSH 72                                // halves per tile row (64 + 8)
#define AT_KH (64 * TSH)                      // 4608 halves
#define AT_STAGE_H (2 * AT_KH)                // K + V
#define Q_OFF_H (AT_STAGE_H * 3)
#define ATTN_SMEM_BYTES ((Q_OFF_H + 128 * TSH) * 2)   // 73728 B

__global__ __launch_bounds__(256, 1)
void attn_fp16_kernel(const __half* __restrict__ qkv, const __half* __restrict__ vt,
                      __half* __restrict__ out) {
    extern __shared__ __half smh[];

    const int tid  = threadIdx.x;
    const int lane = tid & 31;
    const int warp = tid >> 5;
    const int lg = lane >> 2;
    const int lt = lane & 3;
    const int bh = blockIdx.y;
    const int b  = bh >> 4;
    const int h  = bh & 15;
    const int q0 = blockIdx.x * 128;
    const unsigned FULL = 0xffffffffu;

    const size_t base  = (size_t)b * SEQ * 3 * EMB + (size_t)h * HDIM;
    const size_t vbase = (size_t)bh * 64 * SEQ;

    auto ldg_stage = [&](int s, int it) {
        const int c0 = it * 64;
        __half* Ks = smh + s * AT_STAGE_H;
        __half* Vs = Ks + AT_KH;
#pragma unroll
        for (int r = 0; r < 2; r++) {
            int i = tid + r * 256;
            int row = i >> 3, ch = i & 7;
            cp16(smem_u32(&Ks[row * TSH + ch * 8]),
                 &qkv[base + (size_t)(c0 + row) * 3072 + EMB + ch * 8]);
            cp16(smem_u32(&Vs[row * TSH + ch * 8]),
                 &vt[vbase + (size_t)row * SEQ + c0 + ch * 8]);
        }
        CP_COMMIT();
    };

    {
        __half* Qs = smh + Q_OFF_H;
#pragma unroll
        for (int r = 0; r < 4; r++) {
            int i = tid + r * 256;
            int row = i >> 3, ch = i & 7;
            cp16(smem_u32(&Qs[row * TSH + ch * 8]),
                 &qkv[base + (size_t)(q0 + row) * 3072 + ch * 8]);
        }
        CP_COMMIT();
    }
    ldg_stage(0, 0);
    ldg_stage(1, 1);
    ldg_stage(2, 2);

    CP_WAIT3();
    __syncthreads();

    const uint32_t sb = smem_u32(smh);
    const uint32_t q_base = sb + Q_OFF_H * 2 +
        (uint32_t)((warp * 16 + ((lane >> 3) & 1) * 8 + (lane & 7)) * 144 +
                   ((lane >> 4) & 1) * 16);
    const uint32_t kv_off =
        (uint32_t)((((lane >> 4) & 1) * 8 + (lane & 7)) * 144 +
                   ((lane >> 3) & 1) * 16);
    const uint32_t k_base = sb + kv_off;
    const uint32_t v_base = sb + AT_KH * 2 + kv_off;

    uint32_t aq[4][4];
#pragma unroll
    for (int kd = 0; kd < 4; kd++)
        ldsm4(aq[kd], q_base + kd * 32);

    float o[8][4];
#pragma unroll
    for (int ni = 0; ni < 8; ni++)
#pragma unroll
        for (int j = 0; j < 4; j++) o[ni][j] = 0.0f;
    float m0r = -INFINITY, m1r = -INFINITY, l0 = 0.0f, l1 = 0.0f;
    const float scale = 0.03125f;  // EMB^-0.5 (reference scales by full C)

    const int NIT = SEQ / 64;

    for (int t = 0; t < NIT; t++) {
        CP_WAIT2();
        __syncthreads();

        const uint32_t soff = (uint32_t)((t % 3) * AT_STAGE_H * 2);

        // ---- S = Q K^T ----
        float s[8][4];
#pragma unroll
        for (int ni = 0; ni < 8; ni++)
#pragma unroll
            for (int j = 0; j < 4; j++) s[ni][j] = 0.0f;
#pragma unroll
        for (int kd = 0; kd < 4; kd++) {
            uint32_t bk[4][4];
#pragma unroll
            for (int np = 0; np < 4; np++)
                ldsm4(bk[np], k_base + soff + np * (16 * 144) + kd * 32);
#pragma unroll
            for (int np = 0; np < 4; np++) {
                mma_fp16(s[2 * np + 0], aq[kd], &bk[np][0]);
                mma_fp16(s[2 * np + 1], aq[kd], &bk[np][2]);
            }
        }

        // ---- online softmax ----
        float mr0 = -INFINITY, mr1 = -INFINITY;
#pragma unroll
        for (int ni = 0; ni < 8; ni++) {
            mr0 = fmaxf(mr0, fmaxf(s[ni][0], s[ni][1]));
            mr1 = fmaxf(mr1, fmaxf(s[ni][2], s[ni][3]));
        }
#pragma unroll
        for (int off = 1; off <= 2; off <<= 1) {
            mr0 = fmaxf(mr0, __shfl_xor_sync(FULL, mr0, off));
            mr1 = fmaxf(mr1, __shfl_xor_sync(FULL, mr1, off));
        }
        float mn0 = fmaxf(m0r, mr0 * scale);
        float mn1 = fmaxf(m1r, mr1 * scale);
        float f0 = __expf(m0r - mn0);
        float f1 = __expf(m1r - mn1);
        m0r = mn0; m1r = mn1;

        float rs0 = 0.0f, rs1 = 0.0f;
#pragma unroll
        for (int ni = 0; ni < 8; ni++) {
            float p0 = __expf(s[ni][0] * scale - mn0);
            float p1 = __expf(s[ni][1] * scale - mn0);
            float p2 = __expf(s[ni][2] * scale - mn1);
            float p3 = __expf(s[ni][3] * scale - mn1);
            rs0 += p0 + p1;
            rs1 += p2 + p3;
            s[ni][0] = p0; s[ni][1] = p1;
            s[ni][2] = p2; s[ni][3] = p3;
            o[ni][0] *= f0; o[ni][1] *= f0;
            o[ni][2] *= f1; o[ni][3] *= f1;
        }
#pragma unroll
        for (int off = 1; off <= 2; off <<= 1) {
            rs0 += __shfl_xor_sync(FULL, rs0, off);
            rs1 += __shfl_xor_sync(FULL, rs1, off);
        }
        l0 = l0 * f0 + rs0;
        l1 = l1 * f1 + rs1;

        // ---- O += P V ----
#pragma unroll
        for (int kk = 0; kk < 4; kk++) {
            uint32_t pa[4];
            pa[0] = packh2(s[2 * kk][0], s[2 * kk][1]);
            pa[1] = packh2(s[2 * kk][2], s[2 * kk][3]);
            pa[2] = packh2(s[2 * kk + 1][0], s[2 * kk + 1][1]);
            pa[3] = packh2(s[2 * kk + 1][2], s[2 * kk + 1][3]);
            uint32_t bv[4][4];
#pragma unroll
            for (int np = 0; np < 4; np++)
                ldsm4(bv[np], v_base + soff + np * (16 * 144) + kk * 32);
#pragma unroll
            for (int np = 0; np < 4; np++) {
                mma_fp16(o[2 * np + 0], pa, &bv[np][0]);
                mma_fp16(o[2 * np + 1], pa, &bv[np][2]);
            }
        }
        __syncthreads();
        if (t + 3 < NIT) ldg_stage(t % 3, t + 3);
        else CP_COMMIT();
    }

    // ---- normalize, write fp16 [B,N,C] ----
    float inv0 = 1.0f / l0, inv1 = 1.0f / l1;
    int r = q0 + warp * 16 + lg;
#pragma unroll
    for (int ni = 0; ni < 8; ni++) {
        int col = h * HDIM + ni * 8 + 2 * lt;
        *(uint32_t*)&out[((size_t)b * SEQ + r) * EMB + col] =
            packh2(o[ni][0] * inv0, o[ni][1] * inv0);
        *(uint32_t*)&out[((size_t)b * SEQ + r + 8) * EMB + col] =
            packh2(o[ni][2] * inv1, o[ni][3] * inv1);
    }
}

// ---------------------------------------------------------------------------
extern "C" void kernel_launch(void* const* d_in, const int* in_sizes, int n_in,
                              void* d_out, int out_size) {
    const float* x     = (const float*)d_in[0];
    const float* W_qkv = (const float*)d_in[1];
    const float* b_qkv = (const float*)d_in[2];
    const float* W_out = (const float*)d_in[3];
    const float* b_out = (const float*)d_in[4];
    float* out = (float*)d_out;

    __half *qkv, *attn, *xh, *wqkvt, *woutt, *vt;
    cudaGetSymbolAddress((void**)&qkv, g_qkv);
    cudaGetSymbolAddress((void**)&attn, g_attn);
    cudaGetSymbolAddress((void**)&xh, g_xh);
    cudaGetSymbolAddress((void**)&wqkvt, g_wqkvt);
    cudaGetSymbolAddress((void**)&woutt, g_woutt);
    cudaGetSymbolAddress((void**)&vt, g_vt);

    cudaFuncSetAttribute(gemm_fp16_kernel<__half>,
                         cudaFuncAttributeMaxDynamicSharedMemorySize,
                         GEMM_SMEM_BYTES);
    cudaFuncSetAttribute(gemm_fp16_kernel<float>,
                         cudaFuncAttributeMaxDynamicSharedMemorySize,
                         GEMM_SMEM_BYTES);
    cudaFuncSetAttribute(attn_fp16_kernel,
                         cudaFuncAttributeMaxDynamicSharedMemorySize,
                         ATTN_SMEM_BYTES);

    // 0) prep: x -> fp16; weights -> transposed fp16 [N,K]
    {
        int n4 = M_TOT * EMB / 4;
        cvt_h_kernel<<<(n4 + 255) / 256, 256>>>((const float4*)x, (uint2*)xh, n4);
        transpose_h_kernel<<<dim3(QKV_N / 32, EMB / 32), dim3(32, 8)>>>(
            W_qkv, wqkvt, EMB, QKV_N);
        transpose_h_kernel<<<dim3(EMB / 32, EMB / 32), dim3(32, 8)>>>(
            W_out, woutt, EMB, EMB);
    }

    // 1) QKV projection -> fp16 qkv
    gemm_fp16_kernel<__half><<<dim3(QKV_N / 128, M_TOT / 128), 256,
                               GEMM_SMEM_BYTES>>>(
        xh, wqkvt, b_qkv, qkv, M_TOT, QKV_N, EMB);
    // 1b) transpose V for ldmatrix-friendly PV
    transpose_v_kernel<<<dim3(SEQ / 32, HDIM / 32, BATCH * HEADS), dim3(32, 8)>>>(
        qkv, vt);
    // 2) Attention -> fp16 attn
    attn_fp16_kernel<<<dim3(SEQ / 128, BATCH * HEADS), 256, ATTN_SMEM_BYTES>>>(
        qkv, vt, attn);
    // 3) Output projection -> fp32 out
    gemm_fp16_kernel<float><<<dim3(EMB / 128, M_TOT / 128), 256,
                              GEMM_SMEM_BYTES>>>(
        attn, woutt, b_out, out, M_TOT, EMB, EMB);
}